// round 6
// baseline (speedup 1.0000x reference)
#include <cuda_runtime.h>
#include <cuda_fp16.h>
#include <cstdlib>

__attribute__((constructor))
static void hx_set_eager_module_loading() {
    setenv("CUDA_MODULE_LOADING", "EAGER", 1);
}

#define BSZ 4
#define BC  128
#define HH  512
#define LL  8000
#define LT  32

// ---------------- scratch (static device arrays; ~34 MB total) ----------------
__device__ __half g_h[(size_t)BSZ * HH * LL];   // post conv1x1+prelu, fp16 (32.8 MB)
__device__ float2 g_s1[BSZ * LL];               // cLN1: (sum,sumsq) -> (mean,inv_std) in place
__device__ float2 g_s2[BSZ * LL];               // cLN2: same

// ---------------------------------------------------------------------------
// K1: h = prelu(W1 @ x + b1) -> fp16; channel sums of the ROUNDED values.
// Block: 512h x 32l, 256 threads, thread tile 8h x 8l.
// ---------------------------------------------------------------------------
__global__ __launch_bounds__(256) void k1_gemm(
    const float* __restrict__ x, const float* __restrict__ W1,
    const float* __restrict__ b1, const float* __restrict__ a1p)
{
    __shared__ float Xs[BC][36];
    __shared__ float2 red[8][LT];

    const int b  = blockIdx.y;
    const int l0 = blockIdx.x * LT;
    const int tid = threadIdx.x;
    const int hg = tid >> 2;       // 0..63 -> rows hg*8..hg*8+7
    const int lg = tid & 3;        // 0..3  -> cols lg*8..lg*8+7
    const float a1 = __ldg(a1p);

    const float* xb = x + (size_t)b * BC * LL + l0;
    for (int i = tid; i < BC * (LT / 4); i += 256) {
        int c = i >> 3, f = i & 7;
        float4 v = *reinterpret_cast<const float4*>(xb + (size_t)c * LL + f * 4);
        Xs[c][f * 4 + 0] = v.x; Xs[c][f * 4 + 1] = v.y;
        Xs[c][f * 4 + 2] = v.z; Xs[c][f * 4 + 3] = v.w;
    }
    __syncthreads();

    float acc[8][8];
#pragma unroll
    for (int j = 0; j < 8; j++)
#pragma unroll
        for (int i = 0; i < 8; i++) acc[j][i] = 0.f;

    const float* Wp = W1 + (size_t)(hg * 8) * BC;
#pragma unroll 8
    for (int k = 0; k < BC; k++) {
        float4 b0 = *reinterpret_cast<const float4*>(&Xs[k][lg * 8]);
        float4 b1v = *reinterpret_cast<const float4*>(&Xs[k][lg * 8 + 4]);
        float bv[8] = {b0.x, b0.y, b0.z, b0.w, b1v.x, b1v.y, b1v.z, b1v.w};
        float av[8];
#pragma unroll
        for (int j = 0; j < 8; j++) av[j] = __ldg(Wp + j * BC + k);
#pragma unroll
        for (int j = 0; j < 8; j++)
#pragma unroll
            for (int i = 0; i < 8; i++)
                acc[j][i] = fmaf(av[j], bv[i], acc[j][i]);
    }

    float s[8], q[8];
#pragma unroll
    for (int i = 0; i < 8; i++) { s[i] = 0.f; q[i] = 0.f; }

#pragma unroll
    for (int j = 0; j < 8; j++) {
        int h = hg * 8 + j;
        float bb = __ldg(b1 + h);
        __half* op = g_h + ((size_t)b * HH + h) * LL + l0 + lg * 8;
        union { __half2 h2[4]; uint4 u; } pk;
#pragma unroll
        for (int i = 0; i < 4; i++) {
            float v0 = acc[j][2 * i] + bb;
            v0 = (v0 >= 0.f) ? v0 : a1 * v0;
            float v1 = acc[j][2 * i + 1] + bb;
            v1 = (v1 >= 0.f) ? v1 : a1 * v1;
            __half2 hx = __floats2half2_rn(v0, v1);
            float2 vr = __half22float2(hx);
            pk.h2[i] = hx;
            s[2 * i] += vr.x;     q[2 * i] += vr.x * vr.x;
            s[2 * i + 1] += vr.y; q[2 * i + 1] += vr.y * vr.y;
        }
        *reinterpret_cast<uint4*>(op) = pk.u;   // 16B aligned: l0+lg*8 mult of 8
    }

#pragma unroll
    for (int m = 4; m < 32; m <<= 1) {
#pragma unroll
        for (int i = 0; i < 8; i++) {
            s[i] += __shfl_xor_sync(0xffffffffu, s[i], m);
            q[i] += __shfl_xor_sync(0xffffffffu, q[i], m);
        }
    }
    int w = tid >> 5, lane = tid & 31;
    if (lane < 4) {
#pragma unroll
        for (int i = 0; i < 8; i++) red[w][lane * 8 + i] = make_float2(s[i], q[i]);
    }
    __syncthreads();
    if (tid < LT) {
        float cs = 0.f, cq = 0.f;
#pragma unroll
        for (int w2 = 0; w2 < 8; w2++) { float2 v = red[w2][tid]; cs += v.x; cq += v.y; }
        g_s1[b * LL + l0 + tid] = make_float2(cs, cq);
    }
}

// ---------------------------------------------------------------------------
// Scan (IN PLACE): cumulative (sum,sumsq) over L -> (mean, inv_std).
// Buffer selected by `which` IN DEVICE CODE (host cannot pass __device__
// symbol addresses as arguments — that was the round-5 bug).
// ---------------------------------------------------------------------------
__global__ __launch_bounds__(1024) void kscan(int which)
{
    float2* io = (which ? g_s2 : g_s1) + blockIdx.x * LL;
    const int t = threadIdx.x;
    const int lane = t & 31, w = t >> 5;

    float s = 0.f, q = 0.f;
    float ls[8], lq[8];
    const int base = t * 8;
#pragma unroll
    for (int i = 0; i < 8; i++) {
        int l = base + i;
        float2 v = (l < LL) ? io[l] : make_float2(0.f, 0.f);
        s += v.x; q += v.y; ls[i] = s; lq[i] = q;
    }
    float ts = s, tq = q;
#pragma unroll
    for (int d = 1; d < 32; d <<= 1) {
        float us = __shfl_up_sync(0xffffffffu, ts, d);
        float uq = __shfl_up_sync(0xffffffffu, tq, d);
        if (lane >= d) { ts += us; tq += uq; }
    }
    __shared__ float ws[32], wq[32];
    if (lane == 31) { ws[w] = ts; wq[w] = tq; }
    __syncthreads();
    if (w == 0) {
        float as = ws[lane], aq = wq[lane];
#pragma unroll
        for (int d = 1; d < 32; d <<= 1) {
            float us = __shfl_up_sync(0xffffffffu, as, d);
            float uq = __shfl_up_sync(0xffffffffu, aq, d);
            if (lane >= d) { as += us; aq += uq; }
        }
        ws[lane] = as; wq[lane] = aq;
    }
    __syncthreads();
    float offs = ((w > 0) ? ws[w - 1] : 0.f) + (ts - s);
    float offq = ((w > 0) ? wq[w - 1] : 0.f) + (tq - q);
#pragma unroll
    for (int i = 0; i < 8; i++) {
        int l = base + i;
        if (l < LL) {
            float cs = offs + ls[i], cq = offq + lq[i];
            float cnt = 512.0f * (float)(l + 1);
            float mean = cs / cnt;
            float var = fmaxf(cq / cnt - mean * mean, 0.f);
            io[l] = make_float2(mean, rsqrtf(var + 1e-8f));
        }
    }
}

// ---------------------------------------------------------------------------
// K3 (stats only): g = prelu(dwconv(cln1(h)) + db); reduce (sum,sumsq).
// ---------------------------------------------------------------------------
__global__ __launch_bounds__(256) void k3_stats(
    const float* __restrict__ dw, const float* __restrict__ db,
    const float* __restrict__ a2p)
{
    __shared__ float2 smi[LT + 8];
    __shared__ float2 red[8][LT];

    const int b  = blockIdx.y;
    const int l0 = blockIdx.x * LT;
    const int tid = threadIdx.x;
    const int hg = tid >> 2, lg = tid & 3;
    const float a2 = __ldg(a2p);

    if (tid < LT + 8) {
        int l = l0 - 4 + tid;
        smi[tid] = (l >= 0 && l < LL) ? g_s1[b * LL + l] : make_float2(0.f, 0.f);
    }
    __syncthreads();

    float2 m[16];
#pragma unroll
    for (int i = 0; i < 16; i++) m[i] = smi[lg * 8 + i];

    const int s0 = l0 + lg * 8 - 4;
    const bool interior = (s0 >= 0) && (s0 + 16 <= LL);

    float s[8], q[8];
#pragma unroll
    for (int i = 0; i < 8; i++) { s[i] = 0.f; q[i] = 0.f; }

#pragma unroll
    for (int j = 0; j < 8; j++) {
        int h = hg * 8 + j;
        const __half* hp = g_h + ((size_t)b * HH + h) * LL;
        float v[16];
        if (interior) {
            const __half2* p2 = reinterpret_cast<const __half2*>(hp + s0);
#pragma unroll
            for (int i = 0; i < 8; i++) {
                float2 f = __half22float2(p2[i]);
                v[2 * i] = f.x; v[2 * i + 1] = f.y;
            }
        } else {
#pragma unroll
            for (int i = 0; i < 16; i++) {
                int l = s0 + i;
                v[i] = (l >= 0 && l < LL) ? __half2float(hp[l]) : 0.f;
            }
        }
        float hn[16];
#pragma unroll
        for (int i = 0; i < 16; i++) hn[i] = (v[i] - m[i].x) * m[i].y;

        float d0 = __ldg(dw + h * 3 + 0);
        float d1 = __ldg(dw + h * 3 + 1);
        float d2 = __ldg(dw + h * 3 + 2);
        float dbv = __ldg(db + h);

#pragma unroll
        for (int i = 0; i < 8; i++) {
            float y = d0 * hn[i] + d1 * hn[i + 4] + d2 * hn[i + 8] + dbv;
            y = (y >= 0.f) ? y : a2 * y;
            s[i] += y; q[i] += y * y;
        }
    }

#pragma unroll
    for (int mm = 4; mm < 32; mm <<= 1) {
#pragma unroll
        for (int i = 0; i < 8; i++) {
            s[i] += __shfl_xor_sync(0xffffffffu, s[i], mm);
            q[i] += __shfl_xor_sync(0xffffffffu, q[i], mm);
        }
    }
    int w = tid >> 5, lane = tid & 31;
    if (lane < 4) {
#pragma unroll
        for (int i = 0; i < 8; i++) red[w][lane * 8 + i] = make_float2(s[i], q[i]);
    }
    __syncthreads();
    if (tid < LT) {
        float cs = 0.f, cq = 0.f;
#pragma unroll
        for (int w2 = 0; w2 < 8; w2++) { float2 v = red[w2][tid]; cs += v.x; cq += v.y; }
        g_s2[b * LL + l0 + tid] = make_float2(cs, cq);
    }
}

// ---------------------------------------------------------------------------
// K5: recompute gn = cln2(prelu(dwconv(cln1(h)) + db)) per K-chunk, then
// out = Wout @ gn + bout + x ; skip = Wskip @ gn + bskip.
// Block: 256 rows (128 out + 128 skip) x 32 l. Thread tile 8 rows x 4 cols.
// ---------------------------------------------------------------------------
__global__ __launch_bounds__(256) void k5_out(
    const float* __restrict__ Wout, const float* __restrict__ bout,
    const float* __restrict__ Wskip, const float* __restrict__ bskip,
    const float* __restrict__ dw, const float* __restrict__ db,
    const float* __restrict__ a2p,
    const float* __restrict__ x, float* __restrict__ out)
{
    __shared__ float Ws[256][33];
    __shared__ float Gs[32][36];
    __shared__ float2 smi1[LT + 8];
    __shared__ float2 smi2[LT];

    const int b  = blockIdx.y;
    const int l0 = blockIdx.x * LT;
    const int tid = threadIdx.x;
    const int rg = tid >> 3;     // 0..31
    const int lg = tid & 7;      // 0..7
    const float a2 = __ldg(a2p);

    if (tid < LT + 8) {
        int l = l0 - 4 + tid;
        smi1[tid] = (l >= 0 && l < LL) ? g_s1[b * LL + l] : make_float2(0.f, 0.f);
    }
    if (tid < LT) smi2[tid] = g_s2[b * LL + l0 + tid];
    __syncthreads();

    float acc[8][4];
#pragma unroll
    for (int j = 0; j < 8; j++)
#pragma unroll
        for (int i = 0; i < 4; i++) acc[j][i] = 0.f;

    const float* Wbase = (tid < 128) ? (Wout + (size_t)tid * HH)
                                     : (Wskip + (size_t)(tid - 128) * HH);

    float2 m1[12];
#pragma unroll
    for (int i = 0; i < 12; i++) m1[i] = smi1[lg * 4 + i];
    float2 m2[4];
#pragma unroll
    for (int i = 0; i < 4; i++) m2[i] = smi2[lg * 4 + i];

    const int s0 = l0 + lg * 4 - 4;
    const bool interior = (s0 >= 0) && (s0 + 12 <= LL);

    for (int kc = 0; kc < HH; kc += 32) {
        float4 wv[8];
#pragma unroll
        for (int f = 0; f < 8; f++)
            wv[f] = *reinterpret_cast<const float4*>(Wbase + kc + f * 4);

        const int k2 = kc + rg;
        const __half* hp = g_h + ((size_t)b * HH + k2) * LL;
        float v[12];
        if (interior) {
            const __half2* p2 = reinterpret_cast<const __half2*>(hp + s0);
#pragma unroll
            for (int i = 0; i < 6; i++) {
                float2 f = __half22float2(p2[i]);
                v[2 * i] = f.x; v[2 * i + 1] = f.y;
            }
        } else {
#pragma unroll
            for (int i = 0; i < 12; i++) {
                int l = s0 + i;
                v[i] = (l >= 0 && l < LL) ? __half2float(hp[l]) : 0.f;
            }
        }
        float hn[12];
#pragma unroll
        for (int i = 0; i < 12; i++) hn[i] = (v[i] - m1[i].x) * m1[i].y;

        float d0 = __ldg(dw + k2 * 3 + 0);
        float d1 = __ldg(dw + k2 * 3 + 1);
        float d2 = __ldg(dw + k2 * 3 + 2);
        float dbv = __ldg(db + k2);

        float4 nv;
        {
            float gy[4];
#pragma unroll
            for (int i = 0; i < 4; i++) {
                float y = d0 * hn[i] + d1 * hn[i + 4] + d2 * hn[i + 8] + dbv;
                y = (y >= 0.f) ? y : a2 * y;
                gy[i] = (y - m2[i].x) * m2[i].y;
            }
            nv = make_float4(gy[0], gy[1], gy[2], gy[3]);
        }

        __syncthreads();
        *reinterpret_cast<float4*>(&Gs[rg][lg * 4]) = nv;
#pragma unroll
        for (int f = 0; f < 8; f++) {
            Ws[tid][f * 4 + 0] = wv[f].x; Ws[tid][f * 4 + 1] = wv[f].y;
            Ws[tid][f * 4 + 2] = wv[f].z; Ws[tid][f * 4 + 3] = wv[f].w;
        }
        __syncthreads();
#pragma unroll
        for (int kk = 0; kk < 32; kk++) {
            float4 bv = *reinterpret_cast<const float4*>(&Gs[kk][lg * 4]);
            float av[8];
#pragma unroll
            for (int j = 0; j < 8; j++) av[j] = Ws[rg * 8 + j][kk];
#pragma unroll
            for (int j = 0; j < 8; j++) {
                acc[j][0] = fmaf(av[j], bv.x, acc[j][0]);
                acc[j][1] = fmaf(av[j], bv.y, acc[j][1]);
                acc[j][2] = fmaf(av[j], bv.z, acc[j][2]);
                acc[j][3] = fmaf(av[j], bv.w, acc[j][3]);
            }
        }
    }

    const int lcol = l0 + lg * 4;
#pragma unroll
    for (int j = 0; j < 8; j++) {
        int r = rg * 8 + j;
        if (r < 128) {
            float bb = __ldg(bout + r);
            float4 xv = *reinterpret_cast<const float4*>(x + ((size_t)b * BC + r) * LL + lcol);
            float4 o = make_float4(acc[j][0] + bb + xv.x, acc[j][1] + bb + xv.y,
                                   acc[j][2] + bb + xv.z, acc[j][3] + bb + xv.w);
            *reinterpret_cast<float4*>(out + ((size_t)b * BC + r) * LL + lcol) = o;
        } else {
            int r2 = r - 128;
            float bb = __ldg(bskip + r2);
            float4 o = make_float4(acc[j][0] + bb, acc[j][1] + bb,
                                   acc[j][2] + bb, acc[j][3] + bb);
            *reinterpret_cast<float4*>(out + (size_t)BSZ * BC * LL +
                                       ((size_t)b * BC + r2) * LL + lcol) = o;
        }
    }
}

// ---------------------------------------------------------------------------
extern "C" void kernel_launch(void* const* d_in, const int* in_sizes, int n_in,
                              void* d_out, int out_size)
{
    const float* x     = (const float*)d_in[0];
    const float* W1    = (const float*)d_in[1];
    const float* b1    = (const float*)d_in[2];
    const float* dw    = (const float*)d_in[3];
    const float* db    = (const float*)d_in[4];
    const float* Wout  = (const float*)d_in[5];
    const float* bout  = (const float*)d_in[6];
    const float* Wskip = (const float*)d_in[7];
    const float* bskip = (const float*)d_in[8];
    const float* a1    = (const float*)d_in[9];
    const float* a2    = (const float*)d_in[10];
    float* out = (float*)d_out;

    dim3 grid(LL / LT, BSZ);
    k1_gemm<<<grid, 256>>>(x, W1, b1, a1);
    kscan<<<BSZ, 1024>>>(0);
    k3_stats<<<grid, 256>>>(dw, db, a2);
    kscan<<<BSZ, 1024>>>(1);
    k5_out<<<grid, 256>>>(Wout, bout, Wskip, bskip, dw, db, a2, x, out);
}

// round 7
// speedup vs baseline: 1.2966x; 1.2966x over previous
#include <cuda_runtime.h>
#include <cuda_fp16.h>
#include <cstdlib>

__attribute__((constructor))
static void hx_set_eager_module_loading() {
    setenv("CUDA_MODULE_LOADING", "EAGER", 1);
}

#define BSZ 4
#define BC  128
#define HH  512
#define LL  8000
#define LT  32
#define NT5 64   // k5 l-tile

// ---------------- scratch (static device arrays; ~34 MB total) ----------------
__device__ __half g_h[(size_t)BSZ * HH * LL];   // post conv1x1+prelu, fp16 (32.8 MB)
__device__ float2 g_s1[BSZ * LL];               // cLN1 stats (in-place scan)
__device__ float2 g_s2[BSZ * LL];               // cLN2 stats

// ---------------------------------------------------------------------------
// K1: h = prelu(W1 @ x + b1) -> fp16; channel sums of the ROUNDED values.
// (unchanged from round-6 passing version)
// ---------------------------------------------------------------------------
__global__ __launch_bounds__(256) void k1_gemm(
    const float* __restrict__ x, const float* __restrict__ W1,
    const float* __restrict__ b1, const float* __restrict__ a1p)
{
    __shared__ float Xs[BC][36];
    __shared__ float2 red[8][LT];

    const int b  = blockIdx.y;
    const int l0 = blockIdx.x * LT;
    const int tid = threadIdx.x;
    const int hg = tid >> 2;
    const int lg = tid & 3;
    const float a1 = __ldg(a1p);

    const float* xb = x + (size_t)b * BC * LL + l0;
    for (int i = tid; i < BC * (LT / 4); i += 256) {
        int c = i >> 3, f = i & 7;
        float4 v = *reinterpret_cast<const float4*>(xb + (size_t)c * LL + f * 4);
        Xs[c][f * 4 + 0] = v.x; Xs[c][f * 4 + 1] = v.y;
        Xs[c][f * 4 + 2] = v.z; Xs[c][f * 4 + 3] = v.w;
    }
    __syncthreads();

    float acc[8][8];
#pragma unroll
    for (int j = 0; j < 8; j++)
#pragma unroll
        for (int i = 0; i < 8; i++) acc[j][i] = 0.f;

    const float* Wp = W1 + (size_t)(hg * 8) * BC;
#pragma unroll 8
    for (int k = 0; k < BC; k++) {
        float4 b0 = *reinterpret_cast<const float4*>(&Xs[k][lg * 8]);
        float4 b1v = *reinterpret_cast<const float4*>(&Xs[k][lg * 8 + 4]);
        float bv[8] = {b0.x, b0.y, b0.z, b0.w, b1v.x, b1v.y, b1v.z, b1v.w};
        float av[8];
#pragma unroll
        for (int j = 0; j < 8; j++) av[j] = __ldg(Wp + j * BC + k);
#pragma unroll
        for (int j = 0; j < 8; j++)
#pragma unroll
            for (int i = 0; i < 8; i++)
                acc[j][i] = fmaf(av[j], bv[i], acc[j][i]);
    }

    float s[8], q[8];
#pragma unroll
    for (int i = 0; i < 8; i++) { s[i] = 0.f; q[i] = 0.f; }

#pragma unroll
    for (int j = 0; j < 8; j++) {
        int h = hg * 8 + j;
        float bb = __ldg(b1 + h);
        __half* op = g_h + ((size_t)b * HH + h) * LL + l0 + lg * 8;
        union { __half2 h2[4]; uint4 u; } pk;
#pragma unroll
        for (int i = 0; i < 4; i++) {
            float v0 = acc[j][2 * i] + bb;
            v0 = (v0 >= 0.f) ? v0 : a1 * v0;
            float v1 = acc[j][2 * i + 1] + bb;
            v1 = (v1 >= 0.f) ? v1 : a1 * v1;
            __half2 hx = __floats2half2_rn(v0, v1);
            float2 vr = __half22float2(hx);
            pk.h2[i] = hx;
            s[2 * i] += vr.x;     q[2 * i] += vr.x * vr.x;
            s[2 * i + 1] += vr.y; q[2 * i + 1] += vr.y * vr.y;
        }
        *reinterpret_cast<uint4*>(op) = pk.u;
    }

#pragma unroll
    for (int m = 4; m < 32; m <<= 1) {
#pragma unroll
        for (int i = 0; i < 8; i++) {
            s[i] += __shfl_xor_sync(0xffffffffu, s[i], m);
            q[i] += __shfl_xor_sync(0xffffffffu, q[i], m);
        }
    }
    int w = tid >> 5, lane = tid & 31;
    if (lane < 4) {
#pragma unroll
        for (int i = 0; i < 8; i++) red[w][lane * 8 + i] = make_float2(s[i], q[i]);
    }
    __syncthreads();
    if (tid < LT) {
        float cs = 0.f, cq = 0.f;
#pragma unroll
        for (int w2 = 0; w2 < 8; w2++) { float2 v = red[w2][tid]; cs += v.x; cq += v.y; }
        g_s1[b * LL + l0 + tid] = make_float2(cs, cq);
    }
}

// ---------------------------------------------------------------------------
// Scan (IN PLACE): cumulative (sum,sumsq) over L -> (mean, inv_std).
// ---------------------------------------------------------------------------
__global__ __launch_bounds__(1024) void kscan(int which)
{
    float2* io = (which ? g_s2 : g_s1) + blockIdx.x * LL;
    const int t = threadIdx.x;
    const int lane = t & 31, w = t >> 5;

    float s = 0.f, q = 0.f;
    float ls[8], lq[8];
    const int base = t * 8;
#pragma unroll
    for (int i = 0; i < 8; i++) {
        int l = base + i;
        float2 v = (l < LL) ? io[l] : make_float2(0.f, 0.f);
        s += v.x; q += v.y; ls[i] = s; lq[i] = q;
    }
    float ts = s, tq = q;
#pragma unroll
    for (int d = 1; d < 32; d <<= 1) {
        float us = __shfl_up_sync(0xffffffffu, ts, d);
        float uq = __shfl_up_sync(0xffffffffu, tq, d);
        if (lane >= d) { ts += us; tq += uq; }
    }
    __shared__ float ws[32], wq[32];
    if (lane == 31) { ws[w] = ts; wq[w] = tq; }
    __syncthreads();
    if (w == 0) {
        float as = ws[lane], aq = wq[lane];
#pragma unroll
        for (int d = 1; d < 32; d <<= 1) {
            float us = __shfl_up_sync(0xffffffffu, as, d);
            float uq = __shfl_up_sync(0xffffffffu, aq, d);
            if (lane >= d) { as += us; aq += uq; }
        }
        ws[lane] = as; wq[lane] = aq;
    }
    __syncthreads();
    float offs = ((w > 0) ? ws[w - 1] : 0.f) + (ts - s);
    float offq = ((w > 0) ? wq[w - 1] : 0.f) + (tq - q);
#pragma unroll
    for (int i = 0; i < 8; i++) {
        int l = base + i;
        if (l < LL) {
            float cs = offs + ls[i], cq = offq + lq[i];
            float cnt = 512.0f * (float)(l + 1);
            float mean = cs / cnt;
            float var = fmaxf(cq / cnt - mean * mean, 0.f);
            io[l] = make_float2(mean, rsqrtf(var + 1e-8f));
        }
    }
}

// ---------------------------------------------------------------------------
// K3 (stats only): g = prelu(dwconv(cln1(h)) + db); reduce (sum,sumsq).
// (unchanged from round-6 passing version)
// ---------------------------------------------------------------------------
__global__ __launch_bounds__(256) void k3_stats(
    const float* __restrict__ dw, const float* __restrict__ db,
    const float* __restrict__ a2p)
{
    __shared__ float2 smi[LT + 8];
    __shared__ float2 red[8][LT];

    const int b  = blockIdx.y;
    const int l0 = blockIdx.x * LT;
    const int tid = threadIdx.x;
    const int hg = tid >> 2, lg = tid & 3;
    const float a2 = __ldg(a2p);

    if (tid < LT + 8) {
        int l = l0 - 4 + tid;
        smi[tid] = (l >= 0 && l < LL) ? g_s1[b * LL + l] : make_float2(0.f, 0.f);
    }
    __syncthreads();

    float2 m[16];
#pragma unroll
    for (int i = 0; i < 16; i++) m[i] = smi[lg * 8 + i];

    const int s0 = l0 + lg * 8 - 4;
    const bool interior = (s0 >= 0) && (s0 + 16 <= LL);

    float s[8], q[8];
#pragma unroll
    for (int i = 0; i < 8; i++) { s[i] = 0.f; q[i] = 0.f; }

#pragma unroll
    for (int j = 0; j < 8; j++) {
        int h = hg * 8 + j;
        const __half* hp = g_h + ((size_t)b * HH + h) * LL;
        float v[16];
        if (interior) {
            const __half2* p2 = reinterpret_cast<const __half2*>(hp + s0);
#pragma unroll
            for (int i = 0; i < 8; i++) {
                float2 f = __half22float2(p2[i]);
                v[2 * i] = f.x; v[2 * i + 1] = f.y;
            }
        } else {
#pragma unroll
            for (int i = 0; i < 16; i++) {
                int l = s0 + i;
                v[i] = (l >= 0 && l < LL) ? __half2float(hp[l]) : 0.f;
            }
        }
        float hn[16];
#pragma unroll
        for (int i = 0; i < 16; i++) hn[i] = (v[i] - m[i].x) * m[i].y;

        float d0 = __ldg(dw + h * 3 + 0);
        float d1 = __ldg(dw + h * 3 + 1);
        float d2 = __ldg(dw + h * 3 + 2);
        float dbv = __ldg(db + h);

#pragma unroll
        for (int i = 0; i < 8; i++) {
            float y = d0 * hn[i] + d1 * hn[i + 4] + d2 * hn[i + 8] + dbv;
            y = (y >= 0.f) ? y : a2 * y;
            s[i] += y; q[i] += y * y;
        }
    }

#pragma unroll
    for (int mm = 4; mm < 32; mm <<= 1) {
#pragma unroll
        for (int i = 0; i < 8; i++) {
            s[i] += __shfl_xor_sync(0xffffffffu, s[i], mm);
            q[i] += __shfl_xor_sync(0xffffffffu, q[i], mm);
        }
    }
    int w = tid >> 5, lane = tid & 31;
    if (lane < 4) {
#pragma unroll
        for (int i = 0; i < 8; i++) red[w][lane * 8 + i] = make_float2(s[i], q[i]);
    }
    __syncthreads();
    if (tid < LT) {
        float cs = 0.f, cq = 0.f;
#pragma unroll
        for (int w2 = 0; w2 < 8; w2++) { float2 v = red[w2][tid]; cs += v.x; cq += v.y; }
        g_s2[b * LL + l0 + tid] = make_float2(cs, cq);
    }
}

// ---------------------------------------------------------------------------
// HMMA helper: m16n8k16 row.col f32 += f16*f16
// ---------------------------------------------------------------------------
__device__ __forceinline__ void mma16816(
    float c[4], unsigned a0, unsigned a1, unsigned a2, unsigned a3,
    unsigned b0, unsigned b1)
{
    asm volatile(
        "mma.sync.aligned.m16n8k16.row.col.f32.f16.f16.f32 "
        "{%0,%1,%2,%3}, {%4,%5,%6,%7}, {%8,%9}, {%0,%1,%2,%3};"
        : "+f"(c[0]), "+f"(c[1]), "+f"(c[2]), "+f"(c[3])
        : "r"(a0), "r"(a1), "r"(a2), "r"(a3), "r"(b0), "r"(b1));
}

// ---------------------------------------------------------------------------
// K5 (tensor core): gn recomputed on the fly into fp16 smem, W converted to
// fp16 per chunk; C[256][64] = W[256][512] @ gn[512][64] via HMMA.
// Block: 256 thr / 8 warps; warp tile 64x32; K chunks of 64.
// ---------------------------------------------------------------------------
__global__ __launch_bounds__(256) void k5_out_tc(
    const float* __restrict__ Wout, const float* __restrict__ bout,
    const float* __restrict__ Wskip, const float* __restrict__ bskip,
    const float* __restrict__ dw, const float* __restrict__ db,
    const float* __restrict__ a2p,
    const float* __restrict__ x, float* __restrict__ out)
{
    __shared__ __half Ws_h[256][72];     // W chunk  [row][k], pad 8
    __shared__ __half Gs_h[NT5][72];     // gn chunk [n][k]  (B col-major), pad 8
    __shared__ float2 smi1[NT5 + 12];    // cLN1 stats, cols l0-4 .. l0+71
    __shared__ float2 smi2[NT5];         // cLN2 stats, cols l0 .. l0+63

    const int b   = blockIdx.y;
    const int l0  = blockIdx.x * NT5;
    const int tid = threadIdx.x;
    const float a2 = __ldg(a2p);

    if (tid < NT5 + 12) {
        int l = l0 - 4 + tid;
        smi1[tid] = (l >= 0 && l < LL) ? g_s1[b * LL + l] : make_float2(0.f, 0.f);
    }
    if (tid < NT5) smi2[tid] = g_s2[b * LL + l0 + tid];

    const int warp = tid >> 5, lane = tid & 31;
    const int wm = warp >> 1, wn = warp & 1;       // warp tile: rows wm*64, cols wn*32
    const int gq = lane >> 2, tc = lane & 3;

    // producer mapping: thread -> (local channel, 16-col segment)
    const int ch   = tid >> 2;          // 0..63
    const int cseg = tid & 3;           // 0..3
    const int c0   = cseg * 16;
    const int s0   = l0 + c0 - 4;
    const bool interior = (s0 >= 0) && (s0 + 24 <= LL);

    const float* Wrow = (tid < 128) ? (Wout + (size_t)tid * HH)
                                    : (Wskip + (size_t)(tid - 128) * HH);

    float acc[4][4][4];
#pragma unroll
    for (int mt = 0; mt < 4; mt++)
#pragma unroll
        for (int nt = 0; nt < 4; nt++)
#pragma unroll
            for (int i = 0; i < 4; i++) acc[mt][nt][i] = 0.f;

    for (int kc = 0; kc < HH; kc += 64) {
        __syncthreads();   // previous mma phase done (and first-iter smi loads)

        // ---- producer: W chunk fp32 -> fp16 smem ----
        {
            const float* wp = Wrow + kc;
#pragma unroll
            for (int f = 0; f < 16; f++) {
                float4 w4 = *reinterpret_cast<const float4*>(wp + f * 4);
                *reinterpret_cast<__half2*>(&Ws_h[tid][f * 4])     = __floats2half2_rn(w4.x, w4.y);
                *reinterpret_cast<__half2*>(&Ws_h[tid][f * 4 + 2]) = __floats2half2_rn(w4.z, w4.w);
            }
        }

        // ---- producer: gn for channel kc+ch, cols c0..c0+15 ----
        {
            const int k2 = kc + ch;
            const __half* hp = g_h + ((size_t)b * HH + k2) * LL;
            float v[24];
            if (interior) {
#pragma unroll
                for (int i = 0; i < 12; i++) {
                    float2 f = __half22float2(
                        *reinterpret_cast<const __half2*>(hp + s0 + 2 * i));
                    v[2 * i] = f.x; v[2 * i + 1] = f.y;
                }
            } else {
#pragma unroll
                for (int i = 0; i < 24; i++) {
                    int l = s0 + i;
                    v[i] = (l >= 0 && l < LL) ? __half2float(hp[l]) : 0.f;
                }
            }
            float hn[24];
#pragma unroll
            for (int i = 0; i < 24; i++) {
                float2 m = smi1[c0 + i];
                hn[i] = (v[i] - m.x) * m.y;
            }
            float d0 = __ldg(dw + k2 * 3 + 0);
            float d1 = __ldg(dw + k2 * 3 + 1);
            float d2 = __ldg(dw + k2 * 3 + 2);
            float dbv = __ldg(db + k2);
#pragma unroll
            for (int j = 0; j < 16; j++) {
                float y = d0 * hn[j] + d1 * hn[j + 4] + d2 * hn[j + 8] + dbv;
                y = (y >= 0.f) ? y : a2 * y;
                float2 m = smi2[c0 + j];
                Gs_h[c0 + j][ch] = __float2half_rn((y - m.x) * m.y);
            }
        }
        __syncthreads();

        // ---- mma phase ----
#pragma unroll
        for (int kk = 0; kk < 64; kk += 16) {
            unsigned a[4][4];
#pragma unroll
            for (int mt = 0; mt < 4; mt++) {
                int r = wm * 64 + mt * 16 + gq;
                int k = kk + tc * 2;
                a[mt][0] = *reinterpret_cast<unsigned*>(&Ws_h[r][k]);
                a[mt][1] = *reinterpret_cast<unsigned*>(&Ws_h[r + 8][k]);
                a[mt][2] = *reinterpret_cast<unsigned*>(&Ws_h[r][k + 8]);
                a[mt][3] = *reinterpret_cast<unsigned*>(&Ws_h[r + 8][k + 8]);
            }
            unsigned bb[4][2];
#pragma unroll
            for (int nt = 0; nt < 4; nt++) {
                int n = wn * 32 + nt * 8 + gq;
                bb[nt][0] = *reinterpret_cast<unsigned*>(&Gs_h[n][kk + tc * 2]);
                bb[nt][1] = *reinterpret_cast<unsigned*>(&Gs_h[n][kk + tc * 2 + 8]);
            }
#pragma unroll
            for (int mt = 0; mt < 4; mt++)
#pragma unroll
                for (int nt = 0; nt < 4; nt++)
                    mma16816(acc[mt][nt], a[mt][0], a[mt][1], a[mt][2], a[mt][3],
                             bb[nt][0], bb[nt][1]);
        }
    }

    // ---- epilogue ----
    const size_t skip_off = (size_t)BSZ * BC * LL;
#pragma unroll
    for (int mt = 0; mt < 4; mt++) {
        int rbase = wm * 64 + mt * 16 + gq;
#pragma unroll
        for (int nt = 0; nt < 4; nt++) {
            int lcol = l0 + wn * 32 + nt * 8 + tc * 2;
#pragma unroll
            for (int hf = 0; hf < 2; hf++) {
                int r = rbase + hf * 8;
                float o0 = acc[mt][nt][hf * 2 + 0];
                float o1 = acc[mt][nt][hf * 2 + 1];
                if (r < 128) {
                    float bbv = __ldg(bout + r);
                    float2 xv = *reinterpret_cast<const float2*>(
                        x + ((size_t)b * BC + r) * LL + lcol);
                    float2 o = make_float2(o0 + bbv + xv.x, o1 + bbv + xv.y);
                    *reinterpret_cast<float2*>(
                        out + ((size_t)b * BC + r) * LL + lcol) = o;
                } else {
                    int r2 = r - 128;
                    float bbv = __ldg(bskip + r2);
                    float2 o = make_float2(o0 + bbv, o1 + bbv);
                    *reinterpret_cast<float2*>(
                        out + skip_off + ((size_t)b * BC + r2) * LL + lcol) = o;
                }
            }
        }
    }
}

// ---------------------------------------------------------------------------
extern "C" void kernel_launch(void* const* d_in, const int* in_sizes, int n_in,
                              void* d_out, int out_size)
{
    const float* x     = (const float*)d_in[0];
    const float* W1    = (const float*)d_in[1];
    const float* b1    = (const float*)d_in[2];
    const float* dw    = (const float*)d_in[3];
    const float* db    = (const float*)d_in[4];
    const float* Wout  = (const float*)d_in[5];
    const float* bout  = (const float*)d_in[6];
    const float* Wskip = (const float*)d_in[7];
    const float* bskip = (const float*)d_in[8];
    const float* a1    = (const float*)d_in[9];
    const float* a2    = (const float*)d_in[10];
    float* out = (float*)d_out;

    dim3 grid(LL / LT, BSZ);
    k1_gemm<<<grid, 256>>>(x, W1, b1, a1);
    kscan<<<BSZ, 1024>>>(0);
    k3_stats<<<grid, 256>>>(dw, db, a2);
    kscan<<<BSZ, 1024>>>(1);
    dim3 grid5(LL / NT5, BSZ);
    k5_out_tc<<<grid5, 256>>>(Wout, bout, Wskip, bskip, dw, db, a2, x, out);
}

// round 8
// speedup vs baseline: 2.3854x; 1.8397x over previous
#include <cuda_runtime.h>
#include <cuda_fp16.h>
#include <cstdlib>

__attribute__((constructor))
static void hx_set_eager_module_loading() {
    setenv("CUDA_MODULE_LOADING", "EAGER", 1);
}

#define BSZ 4
#define BC  128
#define HH  512
#define LL  8000
#define LT  32
#define NT1 64   // k1 l-tile
#define NT5 64   // k5 l-tile

// ---------------- scratch (static device arrays; ~34 MB total) ----------------
__device__ __half g_h[(size_t)BSZ * HH * LL];   // post conv1x1+prelu, fp16 (32.8 MB)
__device__ float2 g_s1[BSZ * LL];               // cLN1 stats (in-place scan)
__device__ float2 g_s2[BSZ * LL];               // cLN2 stats

// ---------------------------------------------------------------------------
// HMMA helper: m16n8k16 row.col f32 += f16*f16
// ---------------------------------------------------------------------------
__device__ __forceinline__ void mma16816(
    float c[4], unsigned a0, unsigned a1, unsigned a2, unsigned a3,
    unsigned b0, unsigned b1)
{
    asm volatile(
        "mma.sync.aligned.m16n8k16.row.col.f32.f16.f16.f32 "
        "{%0,%1,%2,%3}, {%4,%5,%6,%7}, {%8,%9}, {%0,%1,%2,%3};"
        : "+f"(c[0]), "+f"(c[1]), "+f"(c[2]), "+f"(c[3])
        : "r"(a0), "r"(a1), "r"(a2), "r"(a3), "r"(b0), "r"(b1));
}

// ---------------------------------------------------------------------------
// K1 (tensor core): h[512, NT1] = prelu(W1[512,128] @ x[128, NT1] + b1) -> fp16
// plus per-column (sum,sumsq) of the rounded values.
// 512 threads / 16 warps; warp tile 64x32; K=128 in one pass.
// Dynamic smem: W1 fp16 [512][136] + X fp16 [64][136] + red [16][32]
// ---------------------------------------------------------------------------
#define K1_SMEM (512 * 136 * 2 + NT1 * 136 * 2 + 16 * 32 * 8)

__global__ __launch_bounds__(512) void k1_tc(
    const float* __restrict__ x, const float* __restrict__ W1,
    const float* __restrict__ b1, const float* __restrict__ a1p)
{
    extern __shared__ char sm1[];
    __half (*W1s)[136] = reinterpret_cast<__half(*)[136]>(sm1);
    __half (*Xsh)[136] = reinterpret_cast<__half(*)[136]>(sm1 + 512 * 136 * 2);
    float2 (*red_s)[32] =
        reinterpret_cast<float2(*)[32]>(sm1 + 512 * 136 * 2 + NT1 * 136 * 2);

    const int b   = blockIdx.y;
    const int l0  = blockIdx.x * NT1;
    const int tid = threadIdx.x;
    const float a1 = __ldg(a1p);

    // ---- load W1 (512x128 fp32) -> fp16 smem, coalesced ----
    for (int i = tid; i < 512 * 32; i += 512) {
        int row = i >> 5, f = i & 31;
        float4 w4 = *reinterpret_cast<const float4*>(W1 + (size_t)row * BC + f * 4);
        *reinterpret_cast<__half2*>(&W1s[row][f * 4])     = __floats2half2_rn(w4.x, w4.y);
        *reinterpret_cast<__half2*>(&W1s[row][f * 4 + 2]) = __floats2half2_rn(w4.z, w4.w);
    }

    // ---- load X tile (128ch x 64col fp32) -> fp16 smem [col][ch] ----
    {
        int ch = tid >> 2, cseg = tid & 3;
        const float* xp = x + ((size_t)b * BC + ch) * LL + l0 + cseg * 16;
#pragma unroll
        for (int f = 0; f < 4; f++) {
            float4 v = *reinterpret_cast<const float4*>(xp + f * 4);
            int c = cseg * 16 + f * 4;
            Xsh[c + 0][ch] = __float2half_rn(v.x);
            Xsh[c + 1][ch] = __float2half_rn(v.y);
            Xsh[c + 2][ch] = __float2half_rn(v.z);
            Xsh[c + 3][ch] = __float2half_rn(v.w);
        }
    }
    __syncthreads();

    const int warp = tid >> 5, lane = tid & 31;
    const int wm = warp >> 1, wn = warp & 1;   // rows wm*64.., cols wn*32..
    const int gq = lane >> 2, tc = lane & 3;

    float acc[4][4][4];
#pragma unroll
    for (int mt = 0; mt < 4; mt++)
#pragma unroll
        for (int nt = 0; nt < 4; nt++)
#pragma unroll
            for (int i = 0; i < 4; i++) acc[mt][nt][i] = 0.f;

#pragma unroll
    for (int kk = 0; kk < 128; kk += 16) {
        unsigned a[4][4];
#pragma unroll
        for (int mt = 0; mt < 4; mt++) {
            int r = wm * 64 + mt * 16 + gq;
            int k = kk + tc * 2;
            a[mt][0] = *reinterpret_cast<unsigned*>(&W1s[r][k]);
            a[mt][1] = *reinterpret_cast<unsigned*>(&W1s[r + 8][k]);
            a[mt][2] = *reinterpret_cast<unsigned*>(&W1s[r][k + 8]);
            a[mt][3] = *reinterpret_cast<unsigned*>(&W1s[r + 8][k + 8]);
        }
        unsigned bb[4][2];
#pragma unroll
        for (int nt = 0; nt < 4; nt++) {
            int n = wn * 32 + nt * 8 + gq;
            bb[nt][0] = *reinterpret_cast<unsigned*>(&Xsh[n][kk + tc * 2]);
            bb[nt][1] = *reinterpret_cast<unsigned*>(&Xsh[n][kk + tc * 2 + 8]);
        }
#pragma unroll
        for (int mt = 0; mt < 4; mt++)
#pragma unroll
            for (int nt = 0; nt < 4; nt++)
                mma16816(acc[mt][nt], a[mt][0], a[mt][1], a[mt][2], a[mt][3],
                         bb[nt][0], bb[nt][1]);
    }

    // ---- epilogue: bias + prelu, fp16 store, per-column sums ----
    float ss[8], qq[8];
#pragma unroll
    for (int i = 0; i < 8; i++) { ss[i] = 0.f; qq[i] = 0.f; }

#pragma unroll
    for (int mt = 0; mt < 4; mt++) {
#pragma unroll
        for (int hf = 0; hf < 2; hf++) {
            int row = wm * 64 + mt * 16 + gq + hf * 8;
            float bbv = __ldg(b1 + row);
            __half* hrow = g_h + ((size_t)b * HH + row) * LL + l0 + wn * 32;
#pragma unroll
            for (int nt = 0; nt < 4; nt++) {
                float v0 = acc[mt][nt][hf * 2 + 0] + bbv;
                v0 = (v0 >= 0.f) ? v0 : a1 * v0;
                float v1 = acc[mt][nt][hf * 2 + 1] + bbv;
                v1 = (v1 >= 0.f) ? v1 : a1 * v1;
                __half2 hx = __floats2half2_rn(v0, v1);
                *reinterpret_cast<__half2*>(hrow + nt * 8 + tc * 2) = hx;
                float2 vr = __half22float2(hx);
                ss[nt * 2 + 0] += vr.x; qq[nt * 2 + 0] += vr.x * vr.x;
                ss[nt * 2 + 1] += vr.y; qq[nt * 2 + 1] += vr.y * vr.y;
            }
        }
    }
    // reduce over gq lanes (bits 2..4)
#pragma unroll
    for (int m = 4; m < 32; m <<= 1) {
#pragma unroll
        for (int i = 0; i < 8; i++) {
            ss[i] += __shfl_xor_sync(0xffffffffu, ss[i], m);
            qq[i] += __shfl_xor_sync(0xffffffffu, qq[i], m);
        }
    }
    if (lane < 4) {   // gq==0, tc=lane
#pragma unroll
        for (int nt = 0; nt < 4; nt++) {
            red_s[warp][nt * 8 + tc * 2 + 0] = make_float2(ss[nt * 2 + 0], qq[nt * 2 + 0]);
            red_s[warp][nt * 8 + tc * 2 + 1] = make_float2(ss[nt * 2 + 1], qq[nt * 2 + 1]);
        }
    }
    __syncthreads();
    if (tid < NT1) {
        int wn2 = tid >> 5, c = tid & 31;
        float cs = 0.f, cq = 0.f;
#pragma unroll
        for (int w = 0; w < 8; w++) {
            float2 v = red_s[w * 2 + wn2][c];
            cs += v.x; cq += v.y;
        }
        g_s1[b * LL + l0 + tid] = make_float2(cs, cq);
    }
}

// ---------------------------------------------------------------------------
// Scan (IN PLACE): cumulative (sum,sumsq) over L -> (mean, inv_std).
// ---------------------------------------------------------------------------
__global__ __launch_bounds__(1024) void kscan(int which)
{
    float2* io = (which ? g_s2 : g_s1) + blockIdx.x * LL;
    const int t = threadIdx.x;
    const int lane = t & 31, w = t >> 5;

    float s = 0.f, q = 0.f;
    float ls[8], lq[8];
    const int base = t * 8;
#pragma unroll
    for (int i = 0; i < 8; i++) {
        int l = base + i;
        float2 v = (l < LL) ? io[l] : make_float2(0.f, 0.f);
        s += v.x; q += v.y; ls[i] = s; lq[i] = q;
    }
    float ts = s, tq = q;
#pragma unroll
    for (int d = 1; d < 32; d <<= 1) {
        float us = __shfl_up_sync(0xffffffffu, ts, d);
        float uq = __shfl_up_sync(0xffffffffu, tq, d);
        if (lane >= d) { ts += us; tq += uq; }
    }
    __shared__ float ws[32], wq[32];
    if (lane == 31) { ws[w] = ts; wq[w] = tq; }
    __syncthreads();
    if (w == 0) {
        float as = ws[lane], aq = wq[lane];
#pragma unroll
        for (int d = 1; d < 32; d <<= 1) {
            float us = __shfl_up_sync(0xffffffffu, as, d);
            float uq = __shfl_up_sync(0xffffffffu, aq, d);
            if (lane >= d) { as += us; aq += uq; }
        }
        ws[lane] = as; wq[lane] = aq;
    }
    __syncthreads();
    float offs = ((w > 0) ? ws[w - 1] : 0.f) + (ts - s);
    float offq = ((w > 0) ? wq[w - 1] : 0.f) + (tq - q);
#pragma unroll
    for (int i = 0; i < 8; i++) {
        int l = base + i;
        if (l < LL) {
            float cs = offs + ls[i], cq = offq + lq[i];
            float cnt = 512.0f * (float)(l + 1);
            float mean = cs / cnt;
            float var = fmaxf(cq / cnt - mean * mean, 0.f);
            io[l] = make_float2(mean, rsqrtf(var + 1e-8f));
        }
    }
}

// ---------------------------------------------------------------------------
// K3 (stats only): g = prelu(dwconv(cln1(h)) + db); reduce (sum,sumsq).
// ---------------------------------------------------------------------------
__global__ __launch_bounds__(256) void k3_stats(
    const float* __restrict__ dw, const float* __restrict__ db,
    const float* __restrict__ a2p)
{
    __shared__ float2 smi[LT + 8];
    __shared__ float2 red[8][LT];

    const int b  = blockIdx.y;
    const int l0 = blockIdx.x * LT;
    const int tid = threadIdx.x;
    const int hg = tid >> 2, lg = tid & 3;
    const float a2 = __ldg(a2p);

    if (tid < LT + 8) {
        int l = l0 - 4 + tid;
        smi[tid] = (l >= 0 && l < LL) ? g_s1[b * LL + l] : make_float2(0.f, 0.f);
    }
    __syncthreads();

    float2 m[16];
#pragma unroll
    for (int i = 0; i < 16; i++) m[i] = smi[lg * 8 + i];

    const int s0 = l0 + lg * 8 - 4;
    const bool interior = (s0 >= 0) && (s0 + 16 <= LL);

    float s[8], q[8];
#pragma unroll
    for (int i = 0; i < 8; i++) { s[i] = 0.f; q[i] = 0.f; }

#pragma unroll
    for (int j = 0; j < 8; j++) {
        int h = hg * 8 + j;
        const __half* hp = g_h + ((size_t)b * HH + h) * LL;
        float v[16];
        if (interior) {
            const __half2* p2 = reinterpret_cast<const __half2*>(hp + s0);
#pragma unroll
            for (int i = 0; i < 8; i++) {
                float2 f = __half22float2(p2[i]);
                v[2 * i] = f.x; v[2 * i + 1] = f.y;
            }
        } else {
#pragma unroll
            for (int i = 0; i < 16; i++) {
                int l = s0 + i;
                v[i] = (l >= 0 && l < LL) ? __half2float(hp[l]) : 0.f;
            }
        }
        float hn[16];
#pragma unroll
        for (int i = 0; i < 16; i++) hn[i] = (v[i] - m[i].x) * m[i].y;

        float d0 = __ldg(dw + h * 3 + 0);
        float d1 = __ldg(dw + h * 3 + 1);
        float d2 = __ldg(dw + h * 3 + 2);
        float dbv = __ldg(db + h);

#pragma unroll
        for (int i = 0; i < 8; i++) {
            float y = d0 * hn[i] + d1 * hn[i + 4] + d2 * hn[i + 8] + dbv;
            y = (y >= 0.f) ? y : a2 * y;
            s[i] += y; q[i] += y * y;
        }
    }

#pragma unroll
    for (int mm = 4; mm < 32; mm <<= 1) {
#pragma unroll
        for (int i = 0; i < 8; i++) {
            s[i] += __shfl_xor_sync(0xffffffffu, s[i], mm);
            q[i] += __shfl_xor_sync(0xffffffffu, q[i], mm);
        }
    }
    int w = tid >> 5, lane = tid & 31;
    if (lane < 4) {
#pragma unroll
        for (int i = 0; i < 8; i++) red[w][lane * 8 + i] = make_float2(s[i], q[i]);
    }
    __syncthreads();
    if (tid < LT) {
        float cs = 0.f, cq = 0.f;
#pragma unroll
        for (int w2 = 0; w2 < 8; w2++) { float2 v = red[w2][tid]; cs += v.x; cq += v.y; }
        g_s2[b * LL + l0 + tid] = make_float2(cs, cq);
    }
}

// ---------------------------------------------------------------------------
// K5 (tensor core): gn recomputed on the fly into fp16 smem, W converted to
// fp16 per chunk; C[256][64] = W[256][512] @ gn[512][64] via HMMA.
// (unchanged from round-7 passing version)
// ---------------------------------------------------------------------------
__global__ __launch_bounds__(256) void k5_out_tc(
    const float* __restrict__ Wout, const float* __restrict__ bout,
    const float* __restrict__ Wskip, const float* __restrict__ bskip,
    const float* __restrict__ dw, const float* __restrict__ db,
    const float* __restrict__ a2p,
    const float* __restrict__ x, float* __restrict__ out)
{
    __shared__ __half Ws_h[256][72];
    __shared__ __half Gs_h[NT5][72];
    __shared__ float2 smi1[NT5 + 12];
    __shared__ float2 smi2[NT5];

    const int b   = blockIdx.y;
    const int l0  = blockIdx.x * NT5;
    const int tid = threadIdx.x;
    const float a2 = __ldg(a2p);

    if (tid < NT5 + 12) {
        int l = l0 - 4 + tid;
        smi1[tid] = (l >= 0 && l < LL) ? g_s1[b * LL + l] : make_float2(0.f, 0.f);
    }
    if (tid < NT5) smi2[tid] = g_s2[b * LL + l0 + tid];

    const int warp = tid >> 5, lane = tid & 31;
    const int wm = warp >> 1, wn = warp & 1;
    const int gq = lane >> 2, tc = lane & 3;

    const int ch   = tid >> 2;
    const int cseg = tid & 3;
    const int c0   = cseg * 16;
    const int s0   = l0 + c0 - 4;
    const bool interior = (s0 >= 0) && (s0 + 24 <= LL);

    const float* Wrow = (tid < 128) ? (Wout + (size_t)tid * HH)
                                    : (Wskip + (size_t)(tid - 128) * HH);

    float acc[4][4][4];
#pragma unroll
    for (int mt = 0; mt < 4; mt++)
#pragma unroll
        for (int nt = 0; nt < 4; nt++)
#pragma unroll
            for (int i = 0; i < 4; i++) acc[mt][nt][i] = 0.f;

    for (int kc = 0; kc < HH; kc += 64) {
        __syncthreads();

        {
            const float* wp = Wrow + kc;
#pragma unroll
            for (int f = 0; f < 16; f++) {
                float4 w4 = *reinterpret_cast<const float4*>(wp + f * 4);
                *reinterpret_cast<__half2*>(&Ws_h[tid][f * 4])     = __floats2half2_rn(w4.x, w4.y);
                *reinterpret_cast<__half2*>(&Ws_h[tid][f * 4 + 2]) = __floats2half2_rn(w4.z, w4.w);
            }
        }

        {
            const int k2 = kc + ch;
            const __half* hp = g_h + ((size_t)b * HH + k2) * LL;
            float v[24];
            if (interior) {
#pragma unroll
                for (int i = 0; i < 12; i++) {
                    float2 f = __half22float2(
                        *reinterpret_cast<const __half2*>(hp + s0 + 2 * i));
                    v[2 * i] = f.x; v[2 * i + 1] = f.y;
                }
            } else {
#pragma unroll
                for (int i = 0; i < 24; i++) {
                    int l = s0 + i;
                    v[i] = (l >= 0 && l < LL) ? __half2float(hp[l]) : 0.f;
                }
            }
            float hn[24];
#pragma unroll
            for (int i = 0; i < 24; i++) {
                float2 m = smi1[c0 + i];
                hn[i] = (v[i] - m.x) * m.y;
            }
            float d0 = __ldg(dw + k2 * 3 + 0);
            float d1 = __ldg(dw + k2 * 3 + 1);
            float d2 = __ldg(dw + k2 * 3 + 2);
            float dbv = __ldg(db + k2);
#pragma unroll
            for (int j = 0; j < 16; j++) {
                float y = d0 * hn[j] + d1 * hn[j + 4] + d2 * hn[j + 8] + dbv;
                y = (y >= 0.f) ? y : a2 * y;
                float2 m = smi2[c0 + j];
                Gs_h[c0 + j][ch] = __float2half_rn((y - m.x) * m.y);
            }
        }
        __syncthreads();

#pragma unroll
        for (int kk = 0; kk < 64; kk += 16) {
            unsigned a[4][4];
#pragma unroll
            for (int mt = 0; mt < 4; mt++) {
                int r = wm * 64 + mt * 16 + gq;
                int k = kk + tc * 2;
                a[mt][0] = *reinterpret_cast<unsigned*>(&Ws_h[r][k]);
                a[mt][1] = *reinterpret_cast<unsigned*>(&Ws_h[r + 8][k]);
                a[mt][2] = *reinterpret_cast<unsigned*>(&Ws_h[r][k + 8]);
                a[mt][3] = *reinterpret_cast<unsigned*>(&Ws_h[r + 8][k + 8]);
            }
            unsigned bb[4][2];
#pragma unroll
            for (int nt = 0; nt < 4; nt++) {
                int n = wn * 32 + nt * 8 + gq;
                bb[nt][0] = *reinterpret_cast<unsigned*>(&Gs_h[n][kk + tc * 2]);
                bb[nt][1] = *reinterpret_cast<unsigned*>(&Gs_h[n][kk + tc * 2 + 8]);
            }
#pragma unroll
            for (int mt = 0; mt < 4; mt++)
#pragma unroll
                for (int nt = 0; nt < 4; nt++)
                    mma16816(acc[mt][nt], a[mt][0], a[mt][1], a[mt][2], a[mt][3],
                             bb[nt][0], bb[nt][1]);
        }
    }

    const size_t skip_off = (size_t)BSZ * BC * LL;
#pragma unroll
    for (int mt = 0; mt < 4; mt++) {
        int rbase = wm * 64 + mt * 16 + gq;
#pragma unroll
        for (int nt = 0; nt < 4; nt++) {
            int lcol = l0 + wn * 32 + nt * 8 + tc * 2;
#pragma unroll
            for (int hf = 0; hf < 2; hf++) {
                int r = rbase + hf * 8;
                float o0 = acc[mt][nt][hf * 2 + 0];
                float o1 = acc[mt][nt][hf * 2 + 1];
                if (r < 128) {
                    float bbv = __ldg(bout + r);
                    float2 xv = *reinterpret_cast<const float2*>(
                        x + ((size_t)b * BC + r) * LL + lcol);
                    float2 o = make_float2(o0 + bbv + xv.x, o1 + bbv + xv.y);
                    *reinterpret_cast<float2*>(
                        out + ((size_t)b * BC + r) * LL + lcol) = o;
                } else {
                    int r2 = r - 128;
                    float bbv = __ldg(bskip + r2);
                    float2 o = make_float2(o0 + bbv, o1 + bbv);
                    *reinterpret_cast<float2*>(
                        out + skip_off + ((size_t)b * BC + r2) * LL + lcol) = o;
                }
            }
        }
    }
}

// ---------------------------------------------------------------------------
extern "C" void kernel_launch(void* const* d_in, const int* in_sizes, int n_in,
                              void* d_out, int out_size)
{
    const float* x     = (const float*)d_in[0];
    const float* W1    = (const float*)d_in[1];
    const float* b1    = (const float*)d_in[2];
    const float* dw    = (const float*)d_in[3];
    const float* db    = (const float*)d_in[4];
    const float* Wout  = (const float*)d_in[5];
    const float* bout  = (const float*)d_in[6];
    const float* Wskip = (const float*)d_in[7];
    const float* bskip = (const float*)d_in[8];
    const float* a1    = (const float*)d_in[9];
    const float* a2    = (const float*)d_in[10];
    float* out = (float*)d_out;

    // dynamic smem opt-in (not a stream op; safe under graph capture)
    cudaFuncSetAttribute(k1_tc, cudaFuncAttributeMaxDynamicSharedMemorySize, K1_SMEM);

    dim3 grid1(LL / NT1, BSZ);
    k1_tc<<<grid1, 512, K1_SMEM>>>(x, W1, b1, a1);
    kscan<<<BSZ, 1024>>>(0);
    dim3 grid3(LL / LT, BSZ);
    k3_stats<<<grid3, 256>>>(dw, db, a2);
    kscan<<<BSZ, 1024>>>(1);
    dim3 grid5(LL / NT5, BSZ);
    k5_out_tc<<<grid5, 256>>>(Wout, bout, Wskip, bskip, dw, db, a2, x, out);
}

// round 9
// speedup vs baseline: 2.9008x; 1.2160x over previous
#include <cuda_runtime.h>
#include <cuda_fp16.h>
#include <cstdlib>

__attribute__((constructor))
static void hx_set_eager_module_loading() {
    setenv("CUDA_MODULE_LOADING", "EAGER", 1);
}

#define BSZ 4
#define BC  128
#define HH  512
#define LL  8000
#define LT  32
#define NT1 64   // k1 l-tile
#define NT5 64   // k5 l-tile

// ---------------- scratch (static device arrays; ~34 MB total) ----------------
__device__ __half g_h[(size_t)BSZ * HH * LL];   // post conv1x1+prelu, fp16 (32.8 MB)
__device__ float2 g_s1[BSZ * LL];               // cLN1 stats (in-place scan)
__device__ float2 g_s2[BSZ * LL];               // cLN2 stats

// ---------------------------------------------------------------------------
// HMMA helper: m16n8k16 row.col f32 += f16*f16
// ---------------------------------------------------------------------------
__device__ __forceinline__ void mma16816(
    float c[4], unsigned a0, unsigned a1, unsigned a2, unsigned a3,
    unsigned b0, unsigned b1)
{
    asm volatile(
        "mma.sync.aligned.m16n8k16.row.col.f32.f16.f16.f32 "
        "{%0,%1,%2,%3}, {%4,%5,%6,%7}, {%8,%9}, {%0,%1,%2,%3};"
        : "+f"(c[0]), "+f"(c[1]), "+f"(c[2]), "+f"(c[3])
        : "r"(a0), "r"(a1), "r"(a2), "r"(a3), "r"(b0), "r"(b1));
}

// ---------------------------------------------------------------------------
// K1 (tensor core): h[512, NT1] = prelu(W1[512,128] @ x[128, NT1] + b1) -> fp16
// (unchanged from round-8 passing version)
// ---------------------------------------------------------------------------
#define K1_SMEM (512 * 136 * 2 + NT1 * 136 * 2 + 16 * 32 * 8)

__global__ __launch_bounds__(512) void k1_tc(
    const float* __restrict__ x, const float* __restrict__ W1,
    const float* __restrict__ b1, const float* __restrict__ a1p)
{
    extern __shared__ char sm1[];
    __half (*W1s)[136] = reinterpret_cast<__half(*)[136]>(sm1);
    __half (*Xsh)[136] = reinterpret_cast<__half(*)[136]>(sm1 + 512 * 136 * 2);
    float2 (*red_s)[32] =
        reinterpret_cast<float2(*)[32]>(sm1 + 512 * 136 * 2 + NT1 * 136 * 2);

    const int b   = blockIdx.y;
    const int l0  = blockIdx.x * NT1;
    const int tid = threadIdx.x;
    const float a1 = __ldg(a1p);

    for (int i = tid; i < 512 * 32; i += 512) {
        int row = i >> 5, f = i & 31;
        float4 w4 = *reinterpret_cast<const float4*>(W1 + (size_t)row * BC + f * 4);
        *reinterpret_cast<__half2*>(&W1s[row][f * 4])     = __floats2half2_rn(w4.x, w4.y);
        *reinterpret_cast<__half2*>(&W1s[row][f * 4 + 2]) = __floats2half2_rn(w4.z, w4.w);
    }

    {
        int ch = tid >> 2, cseg = tid & 3;
        const float* xp = x + ((size_t)b * BC + ch) * LL + l0 + cseg * 16;
#pragma unroll
        for (int f = 0; f < 4; f++) {
            float4 v = *reinterpret_cast<const float4*>(xp + f * 4);
            int c = cseg * 16 + f * 4;
            Xsh[c + 0][ch] = __float2half_rn(v.x);
            Xsh[c + 1][ch] = __float2half_rn(v.y);
            Xsh[c + 2][ch] = __float2half_rn(v.z);
            Xsh[c + 3][ch] = __float2half_rn(v.w);
        }
    }
    __syncthreads();

    const int warp = tid >> 5, lane = tid & 31;
    const int wm = warp >> 1, wn = warp & 1;
    const int gq = lane >> 2, tc = lane & 3;

    float acc[4][4][4];
#pragma unroll
    for (int mt = 0; mt < 4; mt++)
#pragma unroll
        for (int nt = 0; nt < 4; nt++)
#pragma unroll
            for (int i = 0; i < 4; i++) acc[mt][nt][i] = 0.f;

#pragma unroll
    for (int kk = 0; kk < 128; kk += 16) {
        unsigned a[4][4];
#pragma unroll
        for (int mt = 0; mt < 4; mt++) {
            int r = wm * 64 + mt * 16 + gq;
            int k = kk + tc * 2;
            a[mt][0] = *reinterpret_cast<unsigned*>(&W1s[r][k]);
            a[mt][1] = *reinterpret_cast<unsigned*>(&W1s[r + 8][k]);
            a[mt][2] = *reinterpret_cast<unsigned*>(&W1s[r][k + 8]);
            a[mt][3] = *reinterpret_cast<unsigned*>(&W1s[r + 8][k + 8]);
        }
        unsigned bb[4][2];
#pragma unroll
        for (int nt = 0; nt < 4; nt++) {
            int n = wn * 32 + nt * 8 + gq;
            bb[nt][0] = *reinterpret_cast<unsigned*>(&Xsh[n][kk + tc * 2]);
            bb[nt][1] = *reinterpret_cast<unsigned*>(&Xsh[n][kk + tc * 2 + 8]);
        }
#pragma unroll
        for (int mt = 0; mt < 4; mt++)
#pragma unroll
            for (int nt = 0; nt < 4; nt++)
                mma16816(acc[mt][nt], a[mt][0], a[mt][1], a[mt][2], a[mt][3],
                         bb[nt][0], bb[nt][1]);
    }

    float ss[8], qq[8];
#pragma unroll
    for (int i = 0; i < 8; i++) { ss[i] = 0.f; qq[i] = 0.f; }

#pragma unroll
    for (int mt = 0; mt < 4; mt++) {
#pragma unroll
        for (int hf = 0; hf < 2; hf++) {
            int row = wm * 64 + mt * 16 + gq + hf * 8;
            float bbv = __ldg(b1 + row);
            __half* hrow = g_h + ((size_t)b * HH + row) * LL + l0 + wn * 32;
#pragma unroll
            for (int nt = 0; nt < 4; nt++) {
                float v0 = acc[mt][nt][hf * 2 + 0] + bbv;
                v0 = (v0 >= 0.f) ? v0 : a1 * v0;
                float v1 = acc[mt][nt][hf * 2 + 1] + bbv;
                v1 = (v1 >= 0.f) ? v1 : a1 * v1;
                __half2 hx = __floats2half2_rn(v0, v1);
                *reinterpret_cast<__half2*>(hrow + nt * 8 + tc * 2) = hx;
                float2 vr = __half22float2(hx);
                ss[nt * 2 + 0] += vr.x; qq[nt * 2 + 0] += vr.x * vr.x;
                ss[nt * 2 + 1] += vr.y; qq[nt * 2 + 1] += vr.y * vr.y;
            }
        }
    }
#pragma unroll
    for (int m = 4; m < 32; m <<= 1) {
#pragma unroll
        for (int i = 0; i < 8; i++) {
            ss[i] += __shfl_xor_sync(0xffffffffu, ss[i], m);
            qq[i] += __shfl_xor_sync(0xffffffffu, qq[i], m);
        }
    }
    if (lane < 4) {
#pragma unroll
        for (int nt = 0; nt < 4; nt++) {
            red_s[warp][nt * 8 + tc * 2 + 0] = make_float2(ss[nt * 2 + 0], qq[nt * 2 + 0]);
            red_s[warp][nt * 8 + tc * 2 + 1] = make_float2(ss[nt * 2 + 1], qq[nt * 2 + 1]);
        }
    }
    __syncthreads();
    if (tid < NT1) {
        int wn2 = tid >> 5, c = tid & 31;
        float cs = 0.f, cq = 0.f;
#pragma unroll
        for (int w = 0; w < 8; w++) {
            float2 v = red_s[w * 2 + wn2][c];
            cs += v.x; cq += v.y;
        }
        g_s1[b * LL + l0 + tid] = make_float2(cs, cq);
    }
}

// ---------------------------------------------------------------------------
// Scan (IN PLACE)  (unchanged)
// ---------------------------------------------------------------------------
__global__ __launch_bounds__(1024) void kscan(int which)
{
    float2* io = (which ? g_s2 : g_s1) + blockIdx.x * LL;
    const int t = threadIdx.x;
    const int lane = t & 31, w = t >> 5;

    float s = 0.f, q = 0.f;
    float ls[8], lq[8];
    const int base = t * 8;
#pragma unroll
    for (int i = 0; i < 8; i++) {
        int l = base + i;
        float2 v = (l < LL) ? io[l] : make_float2(0.f, 0.f);
        s += v.x; q += v.y; ls[i] = s; lq[i] = q;
    }
    float ts = s, tq = q;
#pragma unroll
    for (int d = 1; d < 32; d <<= 1) {
        float us = __shfl_up_sync(0xffffffffu, ts, d);
        float uq = __shfl_up_sync(0xffffffffu, tq, d);
        if (lane >= d) { ts += us; tq += uq; }
    }
    __shared__ float ws[32], wq[32];
    if (lane == 31) { ws[w] = ts; wq[w] = tq; }
    __syncthreads();
    if (w == 0) {
        float as = ws[lane], aq = wq[lane];
#pragma unroll
        for (int d = 1; d < 32; d <<= 1) {
            float us = __shfl_up_sync(0xffffffffu, as, d);
            float uq = __shfl_up_sync(0xffffffffu, aq, d);
            if (lane >= d) { as += us; aq += uq; }
        }
        ws[lane] = as; wq[lane] = aq;
    }
    __syncthreads();
    float offs = ((w > 0) ? ws[w - 1] : 0.f) + (ts - s);
    float offq = ((w > 0) ? wq[w - 1] : 0.f) + (tq - q);
#pragma unroll
    for (int i = 0; i < 8; i++) {
        int l = base + i;
        if (l < LL) {
            float cs = offs + ls[i], cq = offq + lq[i];
            float cnt = 512.0f * (float)(l + 1);
            float mean = cs / cnt;
            float var = fmaxf(cq / cnt - mean * mean, 0.f);
            io[l] = make_float2(mean, rsqrtf(var + 1e-8f));
        }
    }
}

// ---------------------------------------------------------------------------
// K3 (stats only)  (unchanged)
// ---------------------------------------------------------------------------
__global__ __launch_bounds__(256) void k3_stats(
    const float* __restrict__ dw, const float* __restrict__ db,
    const float* __restrict__ a2p)
{
    __shared__ float2 smi[LT + 8];
    __shared__ float2 red[8][LT];

    const int b  = blockIdx.y;
    const int l0 = blockIdx.x * LT;
    const int tid = threadIdx.x;
    const int hg = tid >> 2, lg = tid & 3;
    const float a2 = __ldg(a2p);

    if (tid < LT + 8) {
        int l = l0 - 4 + tid;
        smi[tid] = (l >= 0 && l < LL) ? g_s1[b * LL + l] : make_float2(0.f, 0.f);
    }
    __syncthreads();

    float2 m[16];
#pragma unroll
    for (int i = 0; i < 16; i++) m[i] = smi[lg * 8 + i];

    const int s0 = l0 + lg * 8 - 4;
    const bool interior = (s0 >= 0) && (s0 + 16 <= LL);

    float s[8], q[8];
#pragma unroll
    for (int i = 0; i < 8; i++) { s[i] = 0.f; q[i] = 0.f; }

#pragma unroll
    for (int j = 0; j < 8; j++) {
        int h = hg * 8 + j;
        const __half* hp = g_h + ((size_t)b * HH + h) * LL;
        float v[16];
        if (interior) {
            const __half2* p2 = reinterpret_cast<const __half2*>(hp + s0);
#pragma unroll
            for (int i = 0; i < 8; i++) {
                float2 f = __half22float2(p2[i]);
                v[2 * i] = f.x; v[2 * i + 1] = f.y;
            }
        } else {
#pragma unroll
            for (int i = 0; i < 16; i++) {
                int l = s0 + i;
                v[i] = (l >= 0 && l < LL) ? __half2float(hp[l]) : 0.f;
            }
        }
        float hn[16];
#pragma unroll
        for (int i = 0; i < 16; i++) hn[i] = (v[i] - m[i].x) * m[i].y;

        float d0 = __ldg(dw + h * 3 + 0);
        float d1 = __ldg(dw + h * 3 + 1);
        float d2 = __ldg(dw + h * 3 + 2);
        float dbv = __ldg(db + h);

#pragma unroll
        for (int i = 0; i < 8; i++) {
            float y = d0 * hn[i] + d1 * hn[i + 4] + d2 * hn[i + 8] + dbv;
            y = (y >= 0.f) ? y : a2 * y;
            s[i] += y; q[i] += y * y;
        }
    }

#pragma unroll
    for (int mm = 4; mm < 32; mm <<= 1) {
#pragma unroll
        for (int i = 0; i < 8; i++) {
            s[i] += __shfl_xor_sync(0xffffffffu, s[i], mm);
            q[i] += __shfl_xor_sync(0xffffffffu, q[i], mm);
        }
    }
    int w = tid >> 5, lane = tid & 31;
    if (lane < 4) {
#pragma unroll
        for (int i = 0; i < 8; i++) red[w][lane * 8 + i] = make_float2(s[i], q[i]);
    }
    __syncthreads();
    if (tid < LT) {
        float cs = 0.f, cq = 0.f;
#pragma unroll
        for (int w2 = 0; w2 < 8; w2++) { float2 v = red[w2][tid]; cs += v.x; cq += v.y; }
        g_s2[b * LL + l0 + tid] = make_float2(cs, cq);
    }
}

// ---------------------------------------------------------------------------
// K5 v2 (tensor core, software-pipelined):
//  - coalesced W chunk loads (warp-contiguous rows)
//  - 2-stage smem double buffer; next chunk's gmem loads issued into registers
//    BEFORE the mma phase (latency hidden under mma); ONE barrier per chunk.
// Block: 256 thr / 8 warps; C[256][64] = W[256][512] @ gn[512][64].
// ---------------------------------------------------------------------------
#define K5_W_ELE (256 * 72)
#define K5_G_ELE (NT5 * 72)
#define K5_SMEM  ((2 * K5_W_ELE + 2 * K5_G_ELE) * 2 + (NT5 + 12) * 8 + NT5 * 8)

__global__ __launch_bounds__(256) void k5_tc2(
    const float* __restrict__ Wout, const float* __restrict__ bout,
    const float* __restrict__ Wskip, const float* __restrict__ bskip,
    const float* __restrict__ dw, const float* __restrict__ db,
    const float* __restrict__ a2p,
    const float* __restrict__ x, float* __restrict__ out)
{
    extern __shared__ char sm5[];
    __half* Wsm = reinterpret_cast<__half*>(sm5);                    // [2][256][72]
    __half* Gsm = Wsm + 2 * K5_W_ELE;                                // [2][NT5][72]
    float2* smi1 = reinterpret_cast<float2*>(Gsm + 2 * K5_G_ELE);    // NT5+12
    float2* smi2 = smi1 + (NT5 + 12);                                // NT5

    const int b   = blockIdx.y;
    const int l0  = blockIdx.x * NT5;
    const int tid = threadIdx.x;
    const float a2 = __ldg(a2p);

    if (tid < NT5 + 12) {
        int l = l0 - 4 + tid;
        smi1[tid] = (l >= 0 && l < LL) ? g_s1[b * LL + l] : make_float2(0.f, 0.f);
    }
    if (tid < NT5) smi2[tid] = g_s2[b * LL + l0 + tid];

    const int warp = tid >> 5, lane = tid & 31;
    const int wm = warp >> 1, wn = warp & 1;
    const int gq = lane >> 2, tc = lane & 3;

    // W producer mapping (coalesced): 16 lanes cover one row's 64-float chunk
    const int wrow16 = tid >> 4;     // 0..15
    const int wf     = tid & 15;     // 0..15 -> floats wf*4..wf*4+3

    // gn producer mapping
    const int ch   = tid >> 2;       // 0..63
    const int cseg = tid & 3;        // 0..3
    const int c0   = cseg * 16;
    const int s0   = l0 + c0 - 4;
    const bool interior = (s0 >= 0) && (s0 + 24 <= LL);

    float4   wreg[16];
    unsigned hreg[12];
    float    dreg[4];

    // ---- prefetch helpers (gmem -> regs) ----
    auto prefetch = [&](int kc) {
#pragma unroll
        for (int rp = 0; rp < 16; rp++) {
            const float* src = (rp < 8)
                ? (Wout  + (size_t)(rp * 16 + wrow16) * HH)
                : (Wskip + (size_t)((rp - 8) * 16 + wrow16) * HH);
            wreg[rp] = *reinterpret_cast<const float4*>(src + kc + wf * 4);
        }
        const int k2 = kc + ch;
        const __half* hp = g_h + ((size_t)b * HH + k2) * LL;
        if (interior) {
#pragma unroll
            for (int i = 0; i < 12; i++)
                hreg[i] = *reinterpret_cast<const unsigned*>(hp + s0 + 2 * i);
        } else {
#pragma unroll
            for (int i = 0; i < 12; i++) {
                int la = s0 + 2 * i, lb = la + 1;
                __half h0 = (la >= 0 && la < LL) ? hp[la] : __half(0.f);
                __half h1 = (lb >= 0 && lb < LL) ? hp[lb] : __half(0.f);
                __half2 p = __halves2half2(h0, h1);
                hreg[i] = *reinterpret_cast<unsigned*>(&p);
            }
        }
        dreg[0] = __ldg(dw + k2 * 3 + 0);
        dreg[1] = __ldg(dw + k2 * 3 + 1);
        dreg[2] = __ldg(dw + k2 * 3 + 2);
        dreg[3] = __ldg(db + k2);
    };

    // ---- convert + store regs into stage st ----
    auto store_stage = [&](int st) {
        __half* Wst = Wsm + st * K5_W_ELE;
#pragma unroll
        for (int rp = 0; rp < 16; rp++) {
            int r = rp * 16 + wrow16;
            *reinterpret_cast<__half2*>(&Wst[r * 72 + wf * 4])     = __floats2half2_rn(wreg[rp].x, wreg[rp].y);
            *reinterpret_cast<__half2*>(&Wst[r * 72 + wf * 4 + 2]) = __floats2half2_rn(wreg[rp].z, wreg[rp].w);
        }
        float v[24];
#pragma unroll
        for (int i = 0; i < 12; i++) {
            float2 f = __half22float2(*reinterpret_cast<__half2*>(&hreg[i]));
            v[2 * i] = f.x; v[2 * i + 1] = f.y;
        }
        float hn[24];
#pragma unroll
        for (int i = 0; i < 24; i++) {
            float2 m = smi1[c0 + i];
            hn[i] = (v[i] - m.x) * m.y;
        }
        __half* Gst = Gsm + st * K5_G_ELE;
#pragma unroll
        for (int j = 0; j < 16; j++) {
            float y = dreg[0] * hn[j] + dreg[1] * hn[j + 4] + dreg[2] * hn[j + 8] + dreg[3];
            y = (y >= 0.f) ? y : a2 * y;
            float2 m = smi2[c0 + j];
            Gst[(c0 + j) * 72 + ch] = __float2half_rn((y - m.x) * m.y);
        }
    };

    float acc[4][4][4];
#pragma unroll
    for (int mt = 0; mt < 4; mt++)
#pragma unroll
        for (int nt = 0; nt < 4; nt++)
#pragma unroll
            for (int i = 0; i < 4; i++) acc[mt][nt][i] = 0.f;

    // ---- prologue: chunk 0 ----
    prefetch(0);
    __syncthreads();          // smi1/smi2 visible
    store_stage(0);
    __syncthreads();          // stage 0 ready

    for (int s = 0; s < 8; s++) {
        const int p = s & 1;
        if (s < 7) prefetch((s + 1) * 64);   // latency overlaps mma below

        const __half* Wst = Wsm + p * K5_W_ELE;
        const __half* Gst = Gsm + p * K5_G_ELE;
#pragma unroll
        for (int kk = 0; kk < 64; kk += 16) {
            unsigned a[4][4];
#pragma unroll
            for (int mt = 0; mt < 4; mt++) {
                int r = wm * 64 + mt * 16 + gq;
                int k = kk + tc * 2;
                a[mt][0] = *reinterpret_cast<const unsigned*>(&Wst[r * 72 + k]);
                a[mt][1] = *reinterpret_cast<const unsigned*>(&Wst[(r + 8) * 72 + k]);
                a[mt][2] = *reinterpret_cast<const unsigned*>(&Wst[r * 72 + k + 8]);
                a[mt][3] = *reinterpret_cast<const unsigned*>(&Wst[(r + 8) * 72 + k + 8]);
            }
            unsigned bb[4][2];
#pragma unroll
            for (int nt = 0; nt < 4; nt++) {
                int n = wn * 32 + nt * 8 + gq;
                bb[nt][0] = *reinterpret_cast<const unsigned*>(&Gst[n * 72 + kk + tc * 2]);
                bb[nt][1] = *reinterpret_cast<const unsigned*>(&Gst[n * 72 + kk + tc * 2 + 8]);
            }
#pragma unroll
            for (int mt = 0; mt < 4; mt++)
#pragma unroll
                for (int nt = 0; nt < 4; nt++)
                    mma16816(acc[mt][nt], a[mt][0], a[mt][1], a[mt][2], a[mt][3],
                             bb[nt][0], bb[nt][1]);
        }

        if (s < 7) {
            store_stage(p ^ 1);
            __syncthreads();   // next stage ready; prev stage reads done
        }
    }

    // ---- epilogue ----
    const size_t skip_off = (size_t)BSZ * BC * LL;
#pragma unroll
    for (int mt = 0; mt < 4; mt++) {
        int rbase = wm * 64 + mt * 16 + gq;
#pragma unroll
        for (int nt = 0; nt < 4; nt++) {
            int lcol = l0 + wn * 32 + nt * 8 + tc * 2;
#pragma unroll
            for (int hf = 0; hf < 2; hf++) {
                int r = rbase + hf * 8;
                float o0 = acc[mt][nt][hf * 2 + 0];
                float o1 = acc[mt][nt][hf * 2 + 1];
                if (r < 128) {
                    float bbv = __ldg(bout + r);
                    float2 xv = *reinterpret_cast<const float2*>(
                        x + ((size_t)b * BC + r) * LL + lcol);
                    float2 o = make_float2(o0 + bbv + xv.x, o1 + bbv + xv.y);
                    *reinterpret_cast<float2*>(
                        out + ((size_t)b * BC + r) * LL + lcol) = o;
                } else {
                    int r2 = r - 128;
                    float bbv = __ldg(bskip + r2);
                    float2 o = make_float2(o0 + bbv, o1 + bbv);
                    *reinterpret_cast<float2*>(
                        out + skip_off + ((size_t)b * BC + r2) * LL + lcol) = o;
                }
            }
        }
    }
}

// ---------------------------------------------------------------------------
extern "C" void kernel_launch(void* const* d_in, const int* in_sizes, int n_in,
                              void* d_out, int out_size)
{
    const float* x     = (const float*)d_in[0];
    const float* W1    = (const float*)d_in[1];
    const float* b1    = (const float*)d_in[2];
    const float* dw    = (const float*)d_in[3];
    const float* db    = (const float*)d_in[4];
    const float* Wout  = (const float*)d_in[5];
    const float* bout  = (const float*)d_in[6];
    const float* Wskip = (const float*)d_in[7];
    const float* bskip = (const float*)d_in[8];
    const float* a1    = (const float*)d_in[9];
    const float* a2    = (const float*)d_in[10];
    float* out = (float*)d_out;

    cudaFuncSetAttribute(k1_tc,  cudaFuncAttributeMaxDynamicSharedMemorySize, K1_SMEM);
    cudaFuncSetAttribute(k5_tc2, cudaFuncAttributeMaxDynamicSharedMemorySize, K5_SMEM);

    dim3 grid1(LL / NT1, BSZ);
    k1_tc<<<grid1, 512, K1_SMEM>>>(x, W1, b1, a1);
    kscan<<<BSZ, 1024>>>(0);
    dim3 grid3(LL / LT, BSZ);
    k3_stats<<<grid3, 256>>>(dw, db, a2);
    kscan<<<BSZ, 1024>>>(1);
    dim3 grid5(LL / NT5, BSZ);
    k5_tc2<<<grid5, 256, K5_SMEM>>>(Wout, bout, Wskip, bskip, dw, db, a2, x, out);
}

// round 10
// speedup vs baseline: 3.8252x; 1.3187x over previous
#include <cuda_runtime.h>
#include <cuda_fp16.h>
#include <cstdlib>

__attribute__((constructor))
static void hx_set_eager_module_loading() {
    setenv("CUDA_MODULE_LOADING", "EAGER", 1);
}

#define BSZ 4
#define BC  128
#define HH  512
#define LL  8000
#define LT  32
#define NT1 64   // k1 l-tile
#define NT5 64   // k5 l-tile

// ---------------- scratch (static device arrays; ~66 MB total) ----------------
__device__ __half g_h[(size_t)BSZ * HH * LL];   // post conv1x1+prelu, fp16 (32.8 MB)
__device__ __half g_g[(size_t)BSZ * HH * LL];   // post dwconv+prelu RAW, fp16 (32.8 MB)
__device__ float2 g_s1[BSZ * LL];               // cLN1 stats (in-place scan)
__device__ float2 g_s2[BSZ * LL];               // cLN2 stats
__device__ float  g_rs[256];                    // rowsums of [Wout; Wskip]

// ---------------------------------------------------------------------------
// HMMA helper: m16n8k16 row.col f32 += f16*f16
// ---------------------------------------------------------------------------
__device__ __forceinline__ void mma16816(
    float c[4], unsigned a0, unsigned a1, unsigned a2, unsigned a3,
    unsigned b0, unsigned b1)
{
    asm volatile(
        "mma.sync.aligned.m16n8k16.row.col.f32.f16.f16.f32 "
        "{%0,%1,%2,%3}, {%4,%5,%6,%7}, {%8,%9}, {%0,%1,%2,%3};"
        : "+f"(c[0]), "+f"(c[1]), "+f"(c[2]), "+f"(c[3])
        : "r"(a0), "r"(a1), "r"(a2), "r"(a3), "r"(b0), "r"(b1));
}

// ---------------------------------------------------------------------------
// K1 (tensor core): h = prelu(W1 @ x + b1) -> fp16  (unchanged, passing)
// ---------------------------------------------------------------------------
#define K1_SMEM (512 * 136 * 2 + NT1 * 136 * 2 + 16 * 32 * 8)

__global__ __launch_bounds__(512) void k1_tc(
    const float* __restrict__ x, const float* __restrict__ W1,
    const float* __restrict__ b1, const float* __restrict__ a1p)
{
    extern __shared__ char sm1[];
    __half (*W1s)[136] = reinterpret_cast<__half(*)[136]>(sm1);
    __half (*Xsh)[136] = reinterpret_cast<__half(*)[136]>(sm1 + 512 * 136 * 2);
    float2 (*red_s)[32] =
        reinterpret_cast<float2(*)[32]>(sm1 + 512 * 136 * 2 + NT1 * 136 * 2);

    const int b   = blockIdx.y;
    const int l0  = blockIdx.x * NT1;
    const int tid = threadIdx.x;
    const float a1 = __ldg(a1p);

    for (int i = tid; i < 512 * 32; i += 512) {
        int row = i >> 5, f = i & 31;
        float4 w4 = *reinterpret_cast<const float4*>(W1 + (size_t)row * BC + f * 4);
        *reinterpret_cast<__half2*>(&W1s[row][f * 4])     = __floats2half2_rn(w4.x, w4.y);
        *reinterpret_cast<__half2*>(&W1s[row][f * 4 + 2]) = __floats2half2_rn(w4.z, w4.w);
    }

    {
        int ch = tid >> 2, cseg = tid & 3;
        const float* xp = x + ((size_t)b * BC + ch) * LL + l0 + cseg * 16;
#pragma unroll
        for (int f = 0; f < 4; f++) {
            float4 v = *reinterpret_cast<const float4*>(xp + f * 4);
            int c = cseg * 16 + f * 4;
            Xsh[c + 0][ch] = __float2half_rn(v.x);
            Xsh[c + 1][ch] = __float2half_rn(v.y);
            Xsh[c + 2][ch] = __float2half_rn(v.z);
            Xsh[c + 3][ch] = __float2half_rn(v.w);
        }
    }
    __syncthreads();

    const int warp = tid >> 5, lane = tid & 31;
    const int wm = warp >> 1, wn = warp & 1;
    const int gq = lane >> 2, tc = lane & 3;

    float acc[4][4][4];
#pragma unroll
    for (int mt = 0; mt < 4; mt++)
#pragma unroll
        for (int nt = 0; nt < 4; nt++)
#pragma unroll
            for (int i = 0; i < 4; i++) acc[mt][nt][i] = 0.f;

#pragma unroll
    for (int kk = 0; kk < 128; kk += 16) {
        unsigned a[4][4];
#pragma unroll
        for (int mt = 0; mt < 4; mt++) {
            int r = wm * 64 + mt * 16 + gq;
            int k = kk + tc * 2;
            a[mt][0] = *reinterpret_cast<unsigned*>(&W1s[r][k]);
            a[mt][1] = *reinterpret_cast<unsigned*>(&W1s[r + 8][k]);
            a[mt][2] = *reinterpret_cast<unsigned*>(&W1s[r][k + 8]);
            a[mt][3] = *reinterpret_cast<unsigned*>(&W1s[r + 8][k + 8]);
        }
        unsigned bb[4][2];
#pragma unroll
        for (int nt = 0; nt < 4; nt++) {
            int n = wn * 32 + nt * 8 + gq;
            bb[nt][0] = *reinterpret_cast<unsigned*>(&Xsh[n][kk + tc * 2]);
            bb[nt][1] = *reinterpret_cast<unsigned*>(&Xsh[n][kk + tc * 2 + 8]);
        }
#pragma unroll
        for (int mt = 0; mt < 4; mt++)
#pragma unroll
            for (int nt = 0; nt < 4; nt++)
                mma16816(acc[mt][nt], a[mt][0], a[mt][1], a[mt][2], a[mt][3],
                         bb[nt][0], bb[nt][1]);
    }

    float ss[8], qq[8];
#pragma unroll
    for (int i = 0; i < 8; i++) { ss[i] = 0.f; qq[i] = 0.f; }

#pragma unroll
    for (int mt = 0; mt < 4; mt++) {
#pragma unroll
        for (int hf = 0; hf < 2; hf++) {
            int row = wm * 64 + mt * 16 + gq + hf * 8;
            float bbv = __ldg(b1 + row);
            __half* hrow = g_h + ((size_t)b * HH + row) * LL + l0 + wn * 32;
#pragma unroll
            for (int nt = 0; nt < 4; nt++) {
                float v0 = acc[mt][nt][hf * 2 + 0] + bbv;
                v0 = (v0 >= 0.f) ? v0 : a1 * v0;
                float v1 = acc[mt][nt][hf * 2 + 1] + bbv;
                v1 = (v1 >= 0.f) ? v1 : a1 * v1;
                __half2 hx = __floats2half2_rn(v0, v1);
                *reinterpret_cast<__half2*>(hrow + nt * 8 + tc * 2) = hx;
                float2 vr = __half22float2(hx);
                ss[nt * 2 + 0] += vr.x; qq[nt * 2 + 0] += vr.x * vr.x;
                ss[nt * 2 + 1] += vr.y; qq[nt * 2 + 1] += vr.y * vr.y;
            }
        }
    }
#pragma unroll
    for (int m = 4; m < 32; m <<= 1) {
#pragma unroll
        for (int i = 0; i < 8; i++) {
            ss[i] += __shfl_xor_sync(0xffffffffu, ss[i], m);
            qq[i] += __shfl_xor_sync(0xffffffffu, qq[i], m);
        }
    }
    if (lane < 4) {
#pragma unroll
        for (int nt = 0; nt < 4; nt++) {
            red_s[warp][nt * 8 + tc * 2 + 0] = make_float2(ss[nt * 2 + 0], qq[nt * 2 + 0]);
            red_s[warp][nt * 8 + tc * 2 + 1] = make_float2(ss[nt * 2 + 1], qq[nt * 2 + 1]);
        }
    }
    __syncthreads();
    if (tid < NT1) {
        int wn2 = tid >> 5, c = tid & 31;
        float cs = 0.f, cq = 0.f;
#pragma unroll
        for (int w = 0; w < 8; w++) {
            float2 v = red_s[w * 2 + wn2][c];
            cs += v.x; cq += v.y;
        }
        g_s1[b * LL + l0 + tid] = make_float2(cs, cq);
    }
}

// ---------------------------------------------------------------------------
// Rowsums of [Wout; Wskip]: g_rs[r] = sum_h W[r][h]. 256 blocks x 32 thr.
// ---------------------------------------------------------------------------
__global__ __launch_bounds__(32) void krow(
    const float* __restrict__ Wout, const float* __restrict__ Wskip)
{
    const int r = blockIdx.x;
    const int lane = threadIdx.x;
    const float* src = (r < 128) ? (Wout + (size_t)r * HH)
                                 : (Wskip + (size_t)(r - 128) * HH);
    float s = 0.f;
    for (int i = lane; i < HH / 4; i += 32) {
        float4 v = *reinterpret_cast<const float4*>(src + i * 4);
        s += v.x + v.y + v.z + v.w;
    }
#pragma unroll
    for (int d = 16; d > 0; d >>= 1) s += __shfl_xor_sync(0xffffffffu, s, d);
    if (lane == 0) g_rs[r] = s;
}

// ---------------------------------------------------------------------------
// Scan (IN PLACE)  (unchanged)
// ---------------------------------------------------------------------------
__global__ __launch_bounds__(1024) void kscan(int which)
{
    float2* io = (which ? g_s2 : g_s1) + blockIdx.x * LL;
    const int t = threadIdx.x;
    const int lane = t & 31, w = t >> 5;

    float s = 0.f, q = 0.f;
    float ls[8], lq[8];
    const int base = t * 8;
#pragma unroll
    for (int i = 0; i < 8; i++) {
        int l = base + i;
        float2 v = (l < LL) ? io[l] : make_float2(0.f, 0.f);
        s += v.x; q += v.y; ls[i] = s; lq[i] = q;
    }
    float ts = s, tq = q;
#pragma unroll
    for (int d = 1; d < 32; d <<= 1) {
        float us = __shfl_up_sync(0xffffffffu, ts, d);
        float uq = __shfl_up_sync(0xffffffffu, tq, d);
        if (lane >= d) { ts += us; tq += uq; }
    }
    __shared__ float ws[32], wq[32];
    if (lane == 31) { ws[w] = ts; wq[w] = tq; }
    __syncthreads();
    if (w == 0) {
        float as = ws[lane], aq = wq[lane];
#pragma unroll
        for (int d = 1; d < 32; d <<= 1) {
            float us = __shfl_up_sync(0xffffffffu, as, d);
            float uq = __shfl_up_sync(0xffffffffu, aq, d);
            if (lane >= d) { as += us; aq += uq; }
        }
        ws[lane] = as; wq[lane] = aq;
    }
    __syncthreads();
    float offs = ((w > 0) ? ws[w - 1] : 0.f) + (ts - s);
    float offq = ((w > 0) ? wq[w - 1] : 0.f) + (tq - q);
#pragma unroll
    for (int i = 0; i < 8; i++) {
        int l = base + i;
        if (l < LL) {
            float cs = offs + ls[i], cq = offq + lq[i];
            float cnt = 512.0f * (float)(l + 1);
            float mean = cs / cnt;
            float var = fmaxf(cq / cnt - mean * mean, 0.f);
            io[l] = make_float2(mean, rsqrtf(var + 1e-8f));
        }
    }
}

// ---------------------------------------------------------------------------
// K3: g = prelu(dwconv(cln1(h)) + db); STORE raw g (fp16) + stats of the
// ROUNDED values (so k5's mma sees exactly the values the stats describe).
// ---------------------------------------------------------------------------
__global__ __launch_bounds__(256) void k3_conv(
    const float* __restrict__ dw, const float* __restrict__ db,
    const float* __restrict__ a2p)
{
    __shared__ float2 smi[LT + 8];
    __shared__ float2 red[8][LT];

    const int b  = blockIdx.y;
    const int l0 = blockIdx.x * LT;
    const int tid = threadIdx.x;
    const int hg = tid >> 2, lg = tid & 3;
    const float a2 = __ldg(a2p);

    if (tid < LT + 8) {
        int l = l0 - 4 + tid;
        smi[tid] = (l >= 0 && l < LL) ? g_s1[b * LL + l] : make_float2(0.f, 0.f);
    }
    __syncthreads();

    float2 m[16];
#pragma unroll
    for (int i = 0; i < 16; i++) m[i] = smi[lg * 8 + i];

    const int s0 = l0 + lg * 8 - 4;
    const bool interior = (s0 >= 0) && (s0 + 16 <= LL);

    float s[8], q[8];
#pragma unroll
    for (int i = 0; i < 8; i++) { s[i] = 0.f; q[i] = 0.f; }

#pragma unroll
    for (int j = 0; j < 8; j++) {
        int h = hg * 8 + j;
        const __half* hp = g_h + ((size_t)b * HH + h) * LL;
        float v[16];
        if (interior) {
            const __half2* p2 = reinterpret_cast<const __half2*>(hp + s0);
#pragma unroll
            for (int i = 0; i < 8; i++) {
                float2 f = __half22float2(p2[i]);
                v[2 * i] = f.x; v[2 * i + 1] = f.y;
            }
        } else {
#pragma unroll
            for (int i = 0; i < 16; i++) {
                int l = s0 + i;
                v[i] = (l >= 0 && l < LL) ? __half2float(hp[l]) : 0.f;
            }
        }
        float hn[16];
#pragma unroll
        for (int i = 0; i < 16; i++) hn[i] = (v[i] - m[i].x) * m[i].y;

        float d0 = __ldg(dw + h * 3 + 0);
        float d1 = __ldg(dw + h * 3 + 1);
        float d2 = __ldg(dw + h * 3 + 2);
        float dbv = __ldg(db + h);

        __half* gp = g_g + ((size_t)b * HH + h) * LL + l0 + lg * 8;
        union { __half2 h2[4]; uint4 u; } pk;
#pragma unroll
        for (int i = 0; i < 4; i++) {
            float y0 = d0 * hn[2*i]   + d1 * hn[2*i + 4] + d2 * hn[2*i + 8] + dbv;
            y0 = (y0 >= 0.f) ? y0 : a2 * y0;
            float y1 = d0 * hn[2*i+1] + d1 * hn[2*i + 5] + d2 * hn[2*i + 9] + dbv;
            y1 = (y1 >= 0.f) ? y1 : a2 * y1;
            __half2 hx = __floats2half2_rn(y0, y1);
            pk.h2[i] = hx;
            float2 vr = __half22float2(hx);
            s[2*i]   += vr.x; q[2*i]   += vr.x * vr.x;
            s[2*i+1] += vr.y; q[2*i+1] += vr.y * vr.y;
        }
        *reinterpret_cast<uint4*>(gp) = pk.u;   // 16B aligned
    }

#pragma unroll
    for (int mm = 4; mm < 32; mm <<= 1) {
#pragma unroll
        for (int i = 0; i < 8; i++) {
            s[i] += __shfl_xor_sync(0xffffffffu, s[i], mm);
            q[i] += __shfl_xor_sync(0xffffffffu, q[i], mm);
        }
    }
    int w = tid >> 5, lane = tid & 31;
    if (lane < 4) {
#pragma unroll
        for (int i = 0; i < 8; i++) red[w][lane * 8 + i] = make_float2(s[i], q[i]);
    }
    __syncthreads();
    if (tid < LT) {
        float cs = 0.f, cq = 0.f;
#pragma unroll
        for (int w2 = 0; w2 < 8; w2++) { float2 v = red[w2][tid]; cs += v.x; cq += v.y; }
        g_s2[b * LL + l0 + tid] = make_float2(cs, cq);
    }
}

// ---------------------------------------------------------------------------
// K5 v3: mma on RAW g; cLN2 applied as exact per-column affine in the fp32
// epilogue:  out = s2*acc - s2*m2*rowsum(W) + bias (+x).
// Producer is now a pure fp16 copy (no halo, no arithmetic).
// ---------------------------------------------------------------------------
#define K5_W_ELE (256 * 72)
#define K5_G_ELE (NT5 * 72)
#define K5_SMEM  ((2 * K5_W_ELE + 2 * K5_G_ELE) * 2 + NT5 * 8)

__global__ __launch_bounds__(256) void k5_tc3(
    const float* __restrict__ Wout, const float* __restrict__ bout,
    const float* __restrict__ Wskip, const float* __restrict__ bskip,
    const float* __restrict__ x, float* __restrict__ out)
{
    extern __shared__ char sm5[];
    __half* Wsm = reinterpret_cast<__half*>(sm5);                    // [2][256][72]
    __half* Gsm = Wsm + 2 * K5_W_ELE;                                // [2][NT5][72]
    float2* smi2 = reinterpret_cast<float2*>(Gsm + 2 * K5_G_ELE);    // NT5 (m2, istd2)

    const int b   = blockIdx.y;
    const int l0  = blockIdx.x * NT5;
    const int tid = threadIdx.x;

    if (tid < NT5) smi2[tid] = g_s2[b * LL + l0 + tid];

    const int warp = tid >> 5, lane = tid & 31;
    const int wm = warp >> 1, wn = warp & 1;
    const int gq = lane >> 2, tc = lane & 3;

    // W producer mapping (coalesced)
    const int wrow16 = tid >> 4;     // 0..15
    const int wf     = tid & 15;     // 0..15

    // g producer mapping: 16 contiguous halves per thread
    const int ch   = tid >> 2;       // 0..63 (channel within chunk)
    const int cseg = tid & 3;        // 0..3
    const int c0   = cseg * 16;

    float4 wreg[16];
    uint4  greg[2];

    auto prefetch = [&](int kc) {
#pragma unroll
        for (int rp = 0; rp < 16; rp++) {
            const float* src = (rp < 8)
                ? (Wout  + (size_t)(rp * 16 + wrow16) * HH)
                : (Wskip + (size_t)((rp - 8) * 16 + wrow16) * HH);
            wreg[rp] = *reinterpret_cast<const float4*>(src + kc + wf * 4);
        }
        const __half* gp = g_g + ((size_t)b * HH + kc + ch) * LL + l0 + c0;
        greg[0] = *reinterpret_cast<const uint4*>(gp);       // 8 halves
        greg[1] = *reinterpret_cast<const uint4*>(gp + 8);   // 8 halves
    };

    auto store_stage = [&](int st) {
        __half* Wst = Wsm + st * K5_W_ELE;
#pragma unroll
        for (int rp = 0; rp < 16; rp++) {
            int r = rp * 16 + wrow16;
            *reinterpret_cast<__half2*>(&Wst[r * 72 + wf * 4])     = __floats2half2_rn(wreg[rp].x, wreg[rp].y);
            *reinterpret_cast<__half2*>(&Wst[r * 72 + wf * 4 + 2]) = __floats2half2_rn(wreg[rp].z, wreg[rp].w);
        }
        __half* Gst = Gsm + st * K5_G_ELE;
        const __half* gh = reinterpret_cast<const __half*>(&greg[0]);
#pragma unroll
        for (int j = 0; j < 16; j++)
            Gst[(c0 + j) * 72 + ch] = gh[j];
    };

    float acc[4][4][4];
#pragma unroll
    for (int mt = 0; mt < 4; mt++)
#pragma unroll
        for (int nt = 0; nt < 4; nt++)
#pragma unroll
            for (int i = 0; i < 4; i++) acc[mt][nt][i] = 0.f;

    prefetch(0);
    store_stage(0);
    __syncthreads();          // stage 0 + smi2 ready

    for (int s = 0; s < 8; s++) {
        const int p = s & 1;
        if (s < 7) prefetch((s + 1) * 64);

        const __half* Wst = Wsm + p * K5_W_ELE;
        const __half* Gst = Gsm + p * K5_G_ELE;
#pragma unroll
        for (int kk = 0; kk < 64; kk += 16) {
            unsigned a[4][4];
#pragma unroll
            for (int mt = 0; mt < 4; mt++) {
                int r = wm * 64 + mt * 16 + gq;
                int k = kk + tc * 2;
                a[mt][0] = *reinterpret_cast<const unsigned*>(&Wst[r * 72 + k]);
                a[mt][1] = *reinterpret_cast<const unsigned*>(&Wst[(r + 8) * 72 + k]);
                a[mt][2] = *reinterpret_cast<const unsigned*>(&Wst[r * 72 + k + 8]);
                a[mt][3] = *reinterpret_cast<const unsigned*>(&Wst[(r + 8) * 72 + k + 8]);
            }
            unsigned bb[4][2];
#pragma unroll
            for (int nt = 0; nt < 4; nt++) {
                int n = wn * 32 + nt * 8 + gq;
                bb[nt][0] = *reinterpret_cast<const unsigned*>(&Gst[n * 72 + kk + tc * 2]);
                bb[nt][1] = *reinterpret_cast<const unsigned*>(&Gst[n * 72 + kk + tc * 2 + 8]);
            }
#pragma unroll
            for (int mt = 0; mt < 4; mt++)
#pragma unroll
                for (int nt = 0; nt < 4; nt++)
                    mma16816(acc[mt][nt], a[mt][0], a[mt][1], a[mt][2], a[mt][3],
                             bb[nt][0], bb[nt][1]);
        }

        if (s < 7) {
            store_stage(p ^ 1);
            __syncthreads();
        }
    }

    // ---- epilogue: out = s2*acc - s2*m2*rs + bias (+x) ----
    const size_t skip_off = (size_t)BSZ * BC * LL;
#pragma unroll
    for (int mt = 0; mt < 4; mt++) {
        int rbase = wm * 64 + mt * 16 + gq;
#pragma unroll
        for (int nt = 0; nt < 4; nt++) {
            int nloc = wn * 32 + nt * 8 + tc * 2;
            int lcol = l0 + nloc;
            float2 ms0 = smi2[nloc];
            float2 ms1 = smi2[nloc + 1];
#pragma unroll
            for (int hf = 0; hf < 2; hf++) {
                int r = rbase + hf * 8;
                float rsv = __ldg(g_rs + r);
                float o0 = acc[mt][nt][hf * 2 + 0] * ms0.y - rsv * ms0.x * ms0.y;
                float o1 = acc[mt][nt][hf * 2 + 1] * ms1.y - rsv * ms1.x * ms1.y;
                if (r < 128) {
                    float bbv = __ldg(bout + r);
                    float2 xv = *reinterpret_cast<const float2*>(
                        x + ((size_t)b * BC + r) * LL + lcol);
                    float2 o = make_float2(o0 + bbv + xv.x, o1 + bbv + xv.y);
                    *reinterpret_cast<float2*>(
                        out + ((size_t)b * BC + r) * LL + lcol) = o;
                } else {
                    int r2 = r - 128;
                    float bbv = __ldg(bskip + r2);
                    float2 o = make_float2(o0 + bbv, o1 + bbv);
                    *reinterpret_cast<float2*>(
                        out + skip_off + ((size_t)b * BC + r2) * LL + lcol) = o;
                }
            }
        }
    }
}

// ---------------------------------------------------------------------------
extern "C" void kernel_launch(void* const* d_in, const int* in_sizes, int n_in,
                              void* d_out, int out_size)
{
    const float* x     = (const float*)d_in[0];
    const float* W1    = (const float*)d_in[1];
    const float* b1    = (const float*)d_in[2];
    const float* dw    = (const float*)d_in[3];
    const float* db    = (const float*)d_in[4];
    const float* Wout  = (const float*)d_in[5];
    const float* bout  = (const float*)d_in[6];
    const float* Wskip = (const float*)d_in[7];
    const float* bskip = (const float*)d_in[8];
    const float* a1    = (const float*)d_in[9];
    const float* a2    = (const float*)d_in[10];
    float* out = (float*)d_out;

    cudaFuncSetAttribute(k1_tc,  cudaFuncAttributeMaxDynamicSharedMemorySize, K1_SMEM);
    cudaFuncSetAttribute(k5_tc3, cudaFuncAttributeMaxDynamicSharedMemorySize, K5_SMEM);

    krow<<<256, 32>>>(Wout, Wskip);
    dim3 grid1(LL / NT1, BSZ);
    k1_tc<<<grid1, 512, K1_SMEM>>>(x, W1, b1, a1);
    kscan<<<BSZ, 1024>>>(0);
    dim3 grid3(LL / LT, BSZ);
    k3_conv<<<grid3, 256>>>(dw, db, a2);
    kscan<<<BSZ, 1024>>>(1);
    dim3 grid5(LL / NT5, BSZ);
    k5_tc3<<<grid5, 256, K5_SMEM>>>(Wout, bout, Wskip, bskip, x, out);
}